// round 2
// baseline (speedup 1.0000x reference)
#include <cuda_runtime.h>
#include <cuda_bf16.h>

#define BB 4
#define CN 256
#define NN 4096
#define CR 32
#define OTOT 320   // 32 q + 32 k + 256 v
#define BN_TOT 16384.0f

// ---------------- scratch (device globals; no allocations allowed) ----------------
__device__ float g_mx[CN];
__device__ float g_G[CN * CN];          // Gram sums (atomic accum)
__device__ float g_WfT[CN * OTOT];      // folded weights, transposed [c][o]
__device__ float g_Bf[OTOT];            // folded bias
__device__ float g_Q[BB * NN * CR];     // [b][n][32]
__device__ float g_K[BB * NN * CR];     // [b][n][32]
__device__ float g_V[BB * NN * CN];     // [b][n][256]

// ---------------- zero Gram accumulator ----------------
__global__ void zero_kernel() {
    int i = blockIdx.x * blockDim.x + threadIdx.x;   // 256*256 = 65536
    g_G[i] = 0.0f;
}

// ---------------- per-channel mean of x over (B,N) ----------------
__global__ void mean_kernel(const float* __restrict__ x) {
    int c = blockIdx.x;
    int tid = threadIdx.x;
    float s = 0.0f;
    #pragma unroll 4
    for (int i = 0; i < 64; ++i) {
        int k = tid + i * 256;                 // 0..16383 over (b,n)
        int off = (k >> 12) * (CN * NN) + (k & 4095);
        s += x[off + c * NN];
    }
    __shared__ float red[256];
    red[tid] = s;
    __syncthreads();
    for (int st = 128; st > 0; st >>= 1) {
        if (tid < st) red[tid] += red[tid + st];
        __syncthreads();
    }
    if (tid == 0) g_mx[c] = red[0] * (1.0f / BN_TOT);
}

// ---------------- Gram: G[c,c'] = sum_{b,n} x[b,c,n] x[b,c',n] ----------------
// grid (8,8,16): 32x32 tile, K split 16 ways (1024 k each), atomic accumulate.
__global__ void gram_kernel(const float* __restrict__ x) {
    __shared__ float As[64][33];
    __shared__ float Bs[64][33];
    int c0 = blockIdx.x * 32, c1 = blockIdx.y * 32;
    int kbase = blockIdx.z * 1024;
    int tid = threadIdx.x;
    int ty = tid >> 4, tx = tid & 15;
    float acc00 = 0, acc01 = 0, acc10 = 0, acc11 = 0;
    for (int it = 0; it < 16; ++it) {
        int k0 = kbase + it * 64;
        #pragma unroll
        for (int r = 0; r < 8; ++r) {
            int idx = tid + r * 256;           // 0..2047
            int kk = idx & 63, ci = idx >> 6;  // ci 0..31
            int k = k0 + kk;
            int off = (k >> 12) * (CN * NN) + (k & 4095);
            As[kk][ci] = x[off + (c0 + ci) * NN];
            Bs[kk][ci] = x[off + (c1 + ci) * NN];
        }
        __syncthreads();
        #pragma unroll
        for (int kk = 0; kk < 64; ++kk) {
            float a0 = As[kk][2 * ty], a1 = As[kk][2 * ty + 1];
            float b0 = Bs[kk][2 * tx], b1 = Bs[kk][2 * tx + 1];
            acc00 += a0 * b0; acc01 += a0 * b1;
            acc10 += a1 * b0; acc11 += a1 * b1;
        }
        __syncthreads();
    }
    atomicAdd(&g_G[(c0 + 2 * ty    ) * CN + c1 + 2 * tx    ], acc00);
    atomicAdd(&g_G[(c0 + 2 * ty    ) * CN + c1 + 2 * tx + 1], acc01);
    atomicAdd(&g_G[(c0 + 2 * ty + 1) * CN + c1 + 2 * tx    ], acc10);
    atomicAdd(&g_G[(c0 + 2 * ty + 1) * CN + c1 + 2 * tx + 1], acc11);
}

// ---------------- fold BN into affine conv: Wf = g*rs*w, Bf = b - g*rs*mean ----------------
// one block per output channel o (320 blocks, 256 threads)
__global__ void fold_kernel(const float* __restrict__ w1, const float* __restrict__ w2,
                            const float* __restrict__ w3,
                            const float* __restrict__ g1, const float* __restrict__ b1,
                            const float* __restrict__ g2, const float* __restrict__ b2,
                            const float* __restrict__ g3, const float* __restrict__ b3) {
    int o = blockIdx.x;
    int tid = threadIdx.x;
    const float* w; float gg, bb;
    if (o < 32)       { w = w1 + o * CN;        gg = g1[o];      bb = b1[o]; }
    else if (o < 64)  { w = w2 + (o - 32) * CN; gg = g2[o - 32]; bb = b2[o - 32]; }
    else              { w = w3 + (o - 64) * CN; gg = g3[o - 64]; bb = b3[o - 64]; }

    __shared__ float ws[256];
    __shared__ float redE[256];
    __shared__ float redM[256];
    __shared__ float sc_sh;
    ws[tid] = w[tid];
    __syncthreads();
    // row of G (symmetric): use column-major access for coalescing
    float acc = 0.0f;
    #pragma unroll 4
    for (int c = 0; c < CN; ++c) acc += g_G[c * CN + tid] * ws[c];
    redE[tid] = acc * ws[tid];
    redM[tid] = ws[tid] * g_mx[tid];
    __syncthreads();
    for (int st = 128; st > 0; st >>= 1) {
        if (tid < st) { redE[tid] += redE[tid + st]; redM[tid] += redM[tid + st]; }
        __syncthreads();
    }
    if (tid == 0) {
        float m = redM[0];
        float E = redE[0] * (1.0f / BN_TOT);
        float var = E - m * m;
        float rs = rsqrtf(var + 1e-5f);
        float sc = gg * rs;
        sc_sh = sc;
        g_Bf[o] = bb - sc * m;
    }
    __syncthreads();
    g_WfT[tid * OTOT + o] = sc_sh * ws[tid];
}

// ---------------- fused conv: Z[o,n] = relu(Wf[o,:]·x[b,:,n] + Bf[o]) ----------------
// grid (5, 64, 4), block 256 (16x16, each thread 4x4). Writes Q/K/V transposed.
__global__ void qkd_kernel(const float* __restrict__ x) {
    __shared__ float Ws[16][64];
    __shared__ float Xs[16][64];
    int o0 = blockIdx.x * 64, n0 = blockIdx.y * 64, b = blockIdx.z;
    int tid = threadIdx.x;
    int ty = tid >> 4, tx = tid & 15;
    float acc[4][4] = {};
    const float* xb = x + (size_t)b * CN * NN;
    for (int k0 = 0; k0 < CN; k0 += 16) {
        #pragma unroll
        for (int r = 0; r < 4; ++r) {
            int idx = tid + r * 256;            // 0..1023
            int i = idx & 63, kk = idx >> 6;
            Ws[kk][i] = g_WfT[(k0 + kk) * OTOT + o0 + i];
            Xs[kk][i] = xb[(k0 + kk) * NN + n0 + i];
        }
        __syncthreads();
        #pragma unroll
        for (int kk = 0; kk < 16; ++kk) {
            float4 a = ((const float4*)Ws[kk])[ty];
            float4 bv = ((const float4*)Xs[kk])[tx];
            acc[0][0] += a.x * bv.x; acc[0][1] += a.x * bv.y; acc[0][2] += a.x * bv.z; acc[0][3] += a.x * bv.w;
            acc[1][0] += a.y * bv.x; acc[1][1] += a.y * bv.y; acc[1][2] += a.y * bv.z; acc[1][3] += a.y * bv.w;
            acc[2][0] += a.z * bv.x; acc[2][1] += a.z * bv.y; acc[2][2] += a.z * bv.z; acc[2][3] += a.z * bv.w;
            acc[3][0] += a.w * bv.x; acc[3][1] += a.w * bv.y; acc[3][2] += a.w * bv.z; acc[3][3] += a.w * bv.w;
        }
        __syncthreads();
    }
    #pragma unroll
    for (int i = 0; i < 4; ++i) {
        int o = o0 + ty * 4 + i;
        float bias = g_Bf[o];
        #pragma unroll
        for (int j = 0; j < 4; ++j) {
            int n = n0 + tx * 4 + j;
            float v = fmaxf(acc[i][j] + bias, 0.0f);
            if (o < 32)       g_Q[((size_t)b * NN + n) * CR + o]          = v;
            else if (o < 64)  g_K[((size_t)b * NN + n) * CR + (o - 32)]   = v;
            else              g_V[((size_t)b * NN + n) * CN + (o - 64)]   = v;
        }
    }
}

// ---------------- flash attention + residual ----------------
// grid (128, 4), 256 threads (8 warps). Each warp owns 4 queries x 256 v-channels,
// each lane: 4 queries x 8 channels (2 float4 chunks). MT=32 queries/block, NT=64 keys/tile.
#define MT 32
#define NT 64
#define FLASH_SMEM ((64*33 + 32*65 + 64*256) * 4)

#define FMA4(A, P, V) { A.x += (P)*(V).x; A.y += (P)*(V).y; A.z += (P)*(V).z; A.w += (P)*(V).w; }
#define MUL4(A, F)    { A.x *= (F); A.y *= (F); A.z *= (F); A.w *= (F); }

__global__ void __launch_bounds__(256, 2)
flash_kernel(const float* __restrict__ x, float* __restrict__ out) {
    extern __shared__ float sm[];
    float* Ks = sm;                 // 64*33
    float* Ss = Ks + 64 * 33;       // 32*65
    float* Vs = Ss + 32 * 65;       // 64*256 (float4-aligned offset)
    float4* Vs4 = (float4*)Vs;

    int b = blockIdx.y;
    int m0 = blockIdx.x * MT;
    int tid = threadIdx.x;
    int lane = tid & 31, warp = tid >> 5;
    int q0 = warp * 4;              // local queries q0..q0+3
    int ql = lane & 3;
    int qq = q0 + ql;               // this lane's score-query

    // cache this lane's query row in registers
    float qreg[32];
    {
        const float4* qsrc = (const float4*)(g_Q + ((size_t)b * NN + m0 + qq) * CR);
        #pragma unroll
        for (int j = 0; j < 8; ++j) {
            float4 v = qsrc[j];
            qreg[4 * j + 0] = v.x; qreg[4 * j + 1] = v.y;
            qreg[4 * j + 2] = v.z; qreg[4 * j + 3] = v.w;
        }
    }

    float m_run[4], l_run[4];
    #pragma unroll
    for (int i = 0; i < 4; ++i) { m_run[i] = -1e30f; l_run[i] = 0.0f; }
    float4 acc[4][2];
    #pragma unroll
    for (int i = 0; i < 4; ++i) { acc[i][0] = make_float4(0,0,0,0); acc[i][1] = make_float4(0,0,0,0); }

    for (int n0 = 0; n0 < NN; n0 += NT) {
        // stage K tile [64][32] (padded 33) and V tile [64][256]
        const float* Ksrc = g_K + ((size_t)b * NN + n0) * CR;
        #pragma unroll
        for (int idx = tid; idx < NT * 32; idx += 256)
            Ks[(idx >> 5) * 33 + (idx & 31)] = Ksrc[idx];
        const float4* Vsrc = (const float4*)(g_V + ((size_t)b * NN + n0) * CN);
        #pragma unroll
        for (int idx = tid; idx < NT * 64; idx += 256)
            Vs4[idx] = Vsrc[idx];
        __syncthreads();

        // scores: lane computes s[q=qq][n = (lane>>2) + 8j]
        float s[8];
        #pragma unroll
        for (int j = 0; j < 8; ++j) {
            int n = (lane >> 2) + 8 * j;
            const float* krow = Ks + n * 33;
            float a = 0.0f;
            #pragma unroll
            for (int c = 0; c < 32; ++c) a += qreg[c] * krow[c];
            s[j] = a;
        }
        // tile max over the 8 lanes sharing this q
        float mloc = s[0];
        #pragma unroll
        for (int j = 1; j < 8; ++j) mloc = fmaxf(mloc, s[j]);
        mloc = fmaxf(mloc, __shfl_xor_sync(0xffffffffu, mloc, 4));
        mloc = fmaxf(mloc, __shfl_xor_sync(0xffffffffu, mloc, 8));
        mloc = fmaxf(mloc, __shfl_xor_sync(0xffffffffu, mloc, 16));

        float m_new_q[4], f_q[4];
        #pragma unroll
        for (int i = 0; i < 4; ++i) {
            float tm = __shfl_sync(0xffffffffu, mloc, i, 4);
            float mn = fmaxf(m_run[i], tm);
            f_q[i] = __expf(m_run[i] - mn);
            m_new_q[i] = mn;
        }
        // p for own scores
        float mnown = m_new_q[ql];
        float lsum = 0.0f;
        #pragma unroll
        for (int j = 0; j < 8; ++j) {
            float p = __expf(s[j] - mnown);
            Ss[qq * 65 + (lane >> 2) + 8 * j] = p;
            lsum += p;
        }
        lsum += __shfl_xor_sync(0xffffffffu, lsum, 4);
        lsum += __shfl_xor_sync(0xffffffffu, lsum, 8);
        lsum += __shfl_xor_sync(0xffffffffu, lsum, 16);
        #pragma unroll
        for (int i = 0; i < 4; ++i) {
            float ls = __shfl_sync(0xffffffffu, lsum, i, 4);
            l_run[i] = l_run[i] * f_q[i] + ls;
            m_run[i] = m_new_q[i];
            float f = f_q[i];
            MUL4(acc[i][0], f);
            MUL4(acc[i][1], f);
        }
        __syncwarp();

        // PV: acc[q][c] += sum_n p[q][n] * V[n][c]
        const float* Srow = Ss + q0 * 65;
        #pragma unroll 2
        for (int n = 0; n < NT; ++n) {
            float4 v0 = Vs4[n * 64 + lane];
            float4 v1 = Vs4[n * 64 + 32 + lane];
            float p0 = Srow[n], p1 = Srow[65 + n], p2 = Srow[130 + n], p3 = Srow[195 + n];
            FMA4(acc[0][0], p0, v0); FMA4(acc[0][1], p0, v1);
            FMA4(acc[1][0], p1, v0); FMA4(acc[1][1], p1, v1);
            FMA4(acc[2][0], p2, v0); FMA4(acc[2][1], p2, v1);
            FMA4(acc[3][0], p3, v0); FMA4(acc[3][1], p3, v1);
        }
        __syncthreads();
    }

    // epilogue: divide by l, transpose through shared (reuse Vs), coalesced x + write
    float* Osh = Vs;    // used as [256][33]: 8448 floats <= 16384
    #pragma unroll
    for (int i = 0; i < 4; ++i) {
        float inv = 1.0f / l_run[i];
        int q = q0 + i;
        float4 a0 = acc[i][0], a1 = acc[i][1];
        int c0 = lane * 4;
        Osh[(c0 + 0) * 33 + q] = a0.x * inv;
        Osh[(c0 + 1) * 33 + q] = a0.y * inv;
        Osh[(c0 + 2) * 33 + q] = a0.z * inv;
        Osh[(c0 + 3) * 33 + q] = a0.w * inv;
        Osh[(128 + c0 + 0) * 33 + q] = a1.x * inv;
        Osh[(128 + c0 + 1) * 33 + q] = a1.y * inv;
        Osh[(128 + c0 + 2) * 33 + q] = a1.z * inv;
        Osh[(128 + c0 + 3) * 33 + q] = a1.w * inv;
    }
    __syncthreads();
    const float* xb = x + (size_t)b * CN * NN;
    float* ob = out + (size_t)b * CN * NN;
    for (int r = warp; r < CN; r += 8) {
        float val = Osh[r * 33 + lane];
        ob[(size_t)r * NN + m0 + lane] = xb[(size_t)r * NN + m0 + lane] + val;
    }
}

// ---------------- launcher ----------------
extern "C" void kernel_launch(void* const* d_in, const int* in_sizes, int n_in,
                              void* d_out, int out_size) {
    const float* x  = (const float*)d_in[0];
    const float* w1 = (const float*)d_in[1];
    const float* w2 = (const float*)d_in[2];
    const float* w3 = (const float*)d_in[3];
    const float* g1 = (const float*)d_in[4];
    const float* b1 = (const float*)d_in[5];
    const float* g2 = (const float*)d_in[6];
    const float* b2 = (const float*)d_in[7];
    const float* g3 = (const float*)d_in[8];
    const float* b3 = (const float*)d_in[9];
    float* out = (float*)d_out;

    cudaFuncSetAttribute(flash_kernel, cudaFuncAttributeMaxDynamicSharedMemorySize, FLASH_SMEM);

    zero_kernel<<<256, 256>>>();
    mean_kernel<<<256, 256>>>(x);
    gram_kernel<<<dim3(8, 8, 16), 256>>>(x);
    fold_kernel<<<320, 256>>>(w1, w2, w3, g1, b1, g2, b2, g3, b3);
    qkd_kernel<<<dim3(5, 64, 4), 256>>>(x);
    flash_kernel<<<dim3(128, 4), 256, FLASH_SMEM>>>(x, out);
}

// round 4
// speedup vs baseline: 2.3578x; 2.3578x over previous
#include <cuda_runtime.h>
#include <cuda_bf16.h>
#include <cstdint>

#define BB 4
#define CN 256
#define NN 4096
#define OTOT 320
#define BN_TOT 16384.0f

// ---------------- device scratch ----------------
__device__ float g_mx[CN];
__device__ float g_G[CN * CN];
__device__ float g_WfT[CN * OTOT];
__device__ float g_Bf[OTOT];
__device__ __nv_bfloat16 g_Qb[(size_t)BB * NN * 128]; // [b][n][qhi32|qlo32|qhi32|0]
__device__ __nv_bfloat16 g_Kb[(size_t)BB * NN * 128]; // [b][n][khi32|khi32|klo32|0]
__device__ float g_Vt[(size_t)BB * NN * CN];          // tf32-rounded, [b][n][c]

// ---------------- mma.sync wrappers (base sm_103 compatible) ----------------
__device__ __forceinline__ void mma_bf16_16816(float* c, uint32_t a0, uint32_t a1,
                                               uint32_t a2, uint32_t a3,
                                               uint32_t b0, uint32_t b1) {
    asm volatile("mma.sync.aligned.m16n8k16.row.col.f32.bf16.bf16.f32 "
        "{%0,%1,%2,%3}, {%4,%5,%6,%7}, {%8,%9}, {%0,%1,%2,%3};"
        : "+f"(c[0]), "+f"(c[1]), "+f"(c[2]), "+f"(c[3])
        : "r"(a0), "r"(a1), "r"(a2), "r"(a3), "r"(b0), "r"(b1));
}
__device__ __forceinline__ void mma_tf32_1688(float* c, uint32_t a0, uint32_t a1,
                                              uint32_t a2, uint32_t a3,
                                              uint32_t b0, uint32_t b1) {
    asm volatile("mma.sync.aligned.m16n8k8.row.col.f32.tf32.tf32.f32 "
        "{%0,%1,%2,%3}, {%4,%5,%6,%7}, {%8,%9}, {%0,%1,%2,%3};"
        : "+f"(c[0]), "+f"(c[1]), "+f"(c[2]), "+f"(c[3])
        : "r"(a0), "r"(a1), "r"(a2), "r"(a3), "r"(b0), "r"(b1));
}
__device__ __forceinline__ uint32_t f2tf32(float f) {
    uint32_t u;
    asm("cvt.rn.tf32.f32 %0, %1;" : "=r"(u) : "f"(f));
    return u;
}

// ---------------- prologue: BN folding ----------------
__global__ void zero_kernel() { g_G[blockIdx.x * blockDim.x + threadIdx.x] = 0.0f; }

__global__ void mean_kernel(const float* __restrict__ x) {
    int c = blockIdx.x, tid = threadIdx.x;
    float s = 0.0f;
    #pragma unroll 4
    for (int i = 0; i < 64; ++i) {
        int k = tid + i * 256;
        s += x[(k >> 12) * (CN * NN) + (k & 4095) + c * NN];
    }
    __shared__ float red[256];
    red[tid] = s; __syncthreads();
    for (int st = 128; st > 0; st >>= 1) { if (tid < st) red[tid] += red[tid + st]; __syncthreads(); }
    if (tid == 0) g_mx[c] = red[0] * (1.0f / BN_TOT);
}

__global__ void gram_kernel(const float* __restrict__ x) {
    __shared__ float As[64][33], Bs[64][33];
    int c0 = blockIdx.x * 32, c1 = blockIdx.y * 32, kbase = blockIdx.z * 1024;
    int tid = threadIdx.x, ty = tid >> 4, tx = tid & 15;
    float a00 = 0, a01 = 0, a10 = 0, a11 = 0;
    for (int it = 0; it < 16; ++it) {
        int k0 = kbase + it * 64;
        #pragma unroll
        for (int r = 0; r < 8; ++r) {
            int idx = tid + r * 256, kk = idx & 63, ci = idx >> 6;
            int k = k0 + kk, off = (k >> 12) * (CN * NN) + (k & 4095);
            As[kk][ci] = x[off + (c0 + ci) * NN];
            Bs[kk][ci] = x[off + (c1 + ci) * NN];
        }
        __syncthreads();
        #pragma unroll
        for (int kk = 0; kk < 64; ++kk) {
            float x0 = As[kk][2 * ty], x1 = As[kk][2 * ty + 1];
            float y0 = Bs[kk][2 * tx], y1 = Bs[kk][2 * tx + 1];
            a00 += x0 * y0; a01 += x0 * y1; a10 += x1 * y0; a11 += x1 * y1;
        }
        __syncthreads();
    }
    atomicAdd(&g_G[(c0 + 2 * ty) * CN + c1 + 2 * tx], a00);
    atomicAdd(&g_G[(c0 + 2 * ty) * CN + c1 + 2 * tx + 1], a01);
    atomicAdd(&g_G[(c0 + 2 * ty + 1) * CN + c1 + 2 * tx], a10);
    atomicAdd(&g_G[(c0 + 2 * ty + 1) * CN + c1 + 2 * tx + 1], a11);
}

__global__ void fold_kernel(const float* __restrict__ w1, const float* __restrict__ w2,
                            const float* __restrict__ w3,
                            const float* __restrict__ g1, const float* __restrict__ b1,
                            const float* __restrict__ g2, const float* __restrict__ b2,
                            const float* __restrict__ g3, const float* __restrict__ b3) {
    int o = blockIdx.x, tid = threadIdx.x;
    const float* w; float gg, bb;
    if (o < 32)      { w = w1 + o * CN;        gg = g1[o];      bb = b1[o]; }
    else if (o < 64) { w = w2 + (o - 32) * CN; gg = g2[o - 32]; bb = b2[o - 32]; }
    else             { w = w3 + (o - 64) * CN; gg = g3[o - 64]; bb = b3[o - 64]; }
    __shared__ float ws[256], redE[256], redM[256], sc_sh;
    ws[tid] = w[tid]; __syncthreads();
    float acc = 0.0f;
    #pragma unroll 4
    for (int c = 0; c < CN; ++c) acc += g_G[c * CN + tid] * ws[c];
    redE[tid] = acc * ws[tid];
    redM[tid] = ws[tid] * g_mx[tid];
    __syncthreads();
    for (int st = 128; st > 0; st >>= 1) {
        if (tid < st) { redE[tid] += redE[tid + st]; redM[tid] += redM[tid + st]; }
        __syncthreads();
    }
    if (tid == 0) {
        float m = redM[0], E = redE[0] * (1.0f / BN_TOT);
        float rs = rsqrtf(E - m * m + 1e-5f);
        float sc = gg * rs;
        sc_sh = sc;
        g_Bf[o] = bb - sc * m;
    }
    __syncthreads();
    g_WfT[tid * OTOT + o] = sc_sh * ws[tid];
}

// ---------------- conv+relu -> Qb/Kb (bf16 hi/lo) and Vt (tf32, [b][n][c]) ----------------
__global__ void qkd_kernel(const float* __restrict__ x) {
    __shared__ float Ws[16][64], Xs[16][64];
    int o0 = blockIdx.x * 64, n0 = blockIdx.y * 64, b = blockIdx.z;
    int tid = threadIdx.x, ty = tid >> 4, tx = tid & 15;
    float acc[4][4] = {};
    const float* xb = x + (size_t)b * CN * NN;
    for (int k0 = 0; k0 < CN; k0 += 16) {
        #pragma unroll
        for (int r = 0; r < 4; ++r) {
            int idx = tid + r * 256, i = idx & 63, kk = idx >> 6;
            Ws[kk][i] = g_WfT[(k0 + kk) * OTOT + o0 + i];
            Xs[kk][i] = xb[(k0 + kk) * NN + n0 + i];
        }
        __syncthreads();
        #pragma unroll
        for (int kk = 0; kk < 16; ++kk) {
            float4 a = ((const float4*)Ws[kk])[ty];
            float4 bv = ((const float4*)Xs[kk])[tx];
            acc[0][0] += a.x*bv.x; acc[0][1] += a.x*bv.y; acc[0][2] += a.x*bv.z; acc[0][3] += a.x*bv.w;
            acc[1][0] += a.y*bv.x; acc[1][1] += a.y*bv.y; acc[1][2] += a.y*bv.z; acc[1][3] += a.y*bv.w;
            acc[2][0] += a.z*bv.x; acc[2][1] += a.z*bv.y; acc[2][2] += a.z*bv.z; acc[2][3] += a.z*bv.w;
            acc[3][0] += a.w*bv.x; acc[3][1] += a.w*bv.y; acc[3][2] += a.w*bv.z; acc[3][3] += a.w*bv.w;
        }
        __syncthreads();
    }
    __nv_bfloat16 zero = __float2bfloat16(0.0f);
    #pragma unroll
    for (int i = 0; i < 4; ++i) {
        int o = o0 + ty * 4 + i;
        float bias = g_Bf[o];
        #pragma unroll
        for (int j = 0; j < 4; ++j) {
            int n = n0 + tx * 4 + j;
            float v = fmaxf(acc[i][j] + bias, 0.0f);
            if (o >= 64) {
                g_Vt[((size_t)b * NN + n) * CN + (o - 64)] = __uint_as_float(f2tf32(v));
            } else {
                __nv_bfloat16 hi = __float2bfloat16(v);
                __nv_bfloat16 lo = __float2bfloat16(v - __bfloat162float(hi));
                size_t base = ((size_t)b * NN + n) * 128;
                if (o < 32) {
                    g_Qb[base + o] = hi; g_Qb[base + 32 + o] = lo;
                    g_Qb[base + 64 + o] = hi; g_Qb[base + 96 + o] = zero;
                } else {
                    int oc = o - 32;
                    g_Kb[base + oc] = hi; g_Kb[base + 32 + oc] = hi;
                    g_Kb[base + 64 + oc] = lo; g_Kb[base + 96 + oc] = zero;
                }
            }
        }
    }
}

// ---------------- flash attention via mma.sync ----------------
// Block: 256 thr (8 warps), 64 queries. mrow = wid&3 (16 q), khalf/chalf = wid>>2.
// Chunk NT=32 keys. SMEM (bytes):
//   Qs [64][136] bf16 @0      (17408)
//   Ks [32][136] bf16 @17408  (8704)
//   Vs [32][264] f32  @26112  (33792)
//   Ps [64][36]  f32  @59904  (9216)
//   stM[2][64] f32 @69120, stL[2][64] f32 @69632  -> total 70144
#define QS_OFF 0
#define KS_OFF 17408
#define VS_OFF 26112
#define PS_OFF 59904
#define STM_OFF 69120
#define STL_OFF 69632
#define SM_TOT 70144
#define OSH_OFF 17408   // epilogue reuse: [128][68] f32 = 34816 bytes

__global__ void __launch_bounds__(256, 2)
flash_mma(const float* __restrict__ x, float* __restrict__ out) {
    extern __shared__ __align__(16) char smem[];
    int tid = threadIdx.x;
    int lane = tid & 31, wid = tid >> 5;
    int g = lane >> 2, t = lane & 3;
    int mrow = wid & 3, khalf = wid >> 2;     // khalf doubles as channel-half
    int q0 = mrow * 16;
    int b = blockIdx.y, m0 = blockIdx.x * 64;

    float* stM = (float*)(smem + STM_OFF);
    float* stL = (float*)(smem + STL_OFF);

    // stage Q tile once: 64 rows x 16 uint4 -> padded rows of 17 uint4
    {
        const uint4* qg = (const uint4*)(g_Qb + ((size_t)b * NN + m0) * 128);
        uint4* qs = (uint4*)(smem + QS_OFF);
        #pragma unroll
        for (int i = tid; i < 1024; i += 256) {
            int row = i >> 4, col = i & 15;
            qs[row * 17 + col] = qg[row * 16 + col];
        }
    }

    float D[16][4];
    #pragma unroll
    for (int nt = 0; nt < 16; ++nt) { D[nt][0] = D[nt][1] = D[nt][2] = D[nt][3] = 0.0f; }
    float m_run0 = -1e30f, m_run1 = -1e30f, l_run0 = 0.0f, l_run1 = 0.0f;

    for (int ch = 0; ch < 128; ++ch) {
        int n0 = ch * 32;
        // ---- stage K (32x16 uint4 -> rows of 17) and V (32x64 uint4 -> rows of 66) ----
        {
            const uint4* kg = (const uint4*)(g_Kb + ((size_t)b * NN + n0) * 128);
            uint4* ks = (uint4*)(smem + KS_OFF);
            #pragma unroll
            for (int i = tid; i < 512; i += 256) {
                int row = i >> 4, col = i & 15;
                ks[row * 17 + col] = kg[row * 16 + col];
            }
            const uint4* vg = (const uint4*)(g_Vt + ((size_t)b * NN + n0) * CN);
            uint4* vs = (uint4*)(smem + VS_OFF);
            #pragma unroll
            for (int i = tid; i < 2048; i += 256) {
                int row = i >> 6, col = i & 63;
                vs[row * 66 + col] = vg[row * 64 + col];
            }
        }
        __syncthreads();

        // ---- QK^T: this warp: 16 q (mrow) x 16 keys (khalf), k=96 packed (6 ksteps) ----
        float sc[2][4] = {};
        #pragma unroll
        for (int ks = 0; ks < 6; ++ks) {
            const char* qbase = smem + QS_OFF + (q0 + g) * 272 + ks * 32 + t * 4;
            uint32_t a0 = *(const uint32_t*)(qbase);
            uint32_t a1 = *(const uint32_t*)(qbase + 8 * 272);
            uint32_t a2 = *(const uint32_t*)(qbase + 16);
            uint32_t a3 = *(const uint32_t*)(qbase + 8 * 272 + 16);
            #pragma unroll
            for (int nt = 0; nt < 2; ++nt) {
                const char* kbase = smem + KS_OFF + (khalf * 16 + nt * 8 + g) * 272 + ks * 32 + t * 4;
                uint32_t b0 = *(const uint32_t*)(kbase);
                uint32_t b1 = *(const uint32_t*)(kbase + 16);
                mma_bf16_16816(sc[nt], a0, a1, a2, a3, b0, b1);
            }
        }
        // ---- partial row max over this warp's 16 keys ----
        float mp0 = fmaxf(fmaxf(sc[0][0], sc[0][1]), fmaxf(sc[1][0], sc[1][1]));
        float mp1 = fmaxf(fmaxf(sc[0][2], sc[0][3]), fmaxf(sc[1][2], sc[1][3]));
        mp0 = fmaxf(mp0, __shfl_xor_sync(0xffffffffu, mp0, 1));
        mp0 = fmaxf(mp0, __shfl_xor_sync(0xffffffffu, mp0, 2));
        mp1 = fmaxf(mp1, __shfl_xor_sync(0xffffffffu, mp1, 1));
        mp1 = fmaxf(mp1, __shfl_xor_sync(0xffffffffu, mp1, 2));
        if (t == 0) {
            stM[khalf * 64 + q0 + g] = mp0;
            stM[khalf * 64 + q0 + 8 + g] = mp1;
        }
        __syncthreads();
        // ---- combine halves, online rescale, exp, store P (tf32) ----
        float mt0 = fmaxf(stM[q0 + g], stM[64 + q0 + g]);
        float mt1 = fmaxf(stM[q0 + 8 + g], stM[64 + q0 + 8 + g]);
        float mn0 = fmaxf(m_run0, mt0), mn1 = fmaxf(m_run1, mt1);
        float f0 = __expf(m_run0 - mn0), f1 = __expf(m_run1 - mn1);
        m_run0 = mn0; m_run1 = mn1;
        float ls0 = 0.0f, ls1 = 0.0f;
        #pragma unroll
        for (int nt = 0; nt < 2; ++nt) {
            float p0 = __expf(sc[nt][0] - mn0);
            float p1 = __expf(sc[nt][1] - mn0);
            float p2 = __expf(sc[nt][2] - mn1);
            float p3 = __expf(sc[nt][3] - mn1);
            ls0 += p0 + p1; ls1 += p2 + p3;
            int col = khalf * 16 + nt * 8 + 2 * t;
            uint32_t* pr0 = (uint32_t*)(smem + PS_OFF + (q0 + g) * 144 + col * 4);
            uint32_t* pr1 = (uint32_t*)(smem + PS_OFF + (q0 + 8 + g) * 144 + col * 4);
            pr0[0] = f2tf32(p0); pr0[1] = f2tf32(p1);
            pr1[0] = f2tf32(p2); pr1[1] = f2tf32(p3);
        }
        ls0 += __shfl_xor_sync(0xffffffffu, ls0, 1);
        ls0 += __shfl_xor_sync(0xffffffffu, ls0, 2);
        ls1 += __shfl_xor_sync(0xffffffffu, ls1, 1);
        ls1 += __shfl_xor_sync(0xffffffffu, ls1, 2);
        if (t == 0) {
            stL[khalf * 64 + q0 + g] = ls0;
            stL[khalf * 64 + q0 + 8 + g] = ls1;
        }
        // rescale accumulators
        #pragma unroll
        for (int nt = 0; nt < 16; ++nt) {
            D[nt][0] *= f0; D[nt][1] *= f0;
            D[nt][2] *= f1; D[nt][3] *= f1;
        }
        __syncthreads();
        l_run0 = l_run0 * f0 + stL[q0 + g] + stL[64 + q0 + g];
        l_run1 = l_run1 * f1 + stL[q0 + 8 + g] + stL[64 + q0 + 8 + g];

        // ---- PV: D[16q][128c] += P[16q][32k] * V[32k][128c] (tf32) ----
        uint32_t pa[4][4];
        #pragma unroll
        for (int ks = 0; ks < 4; ++ks) {
            const char* pbase = smem + PS_OFF + (q0 + g) * 144 + ks * 32 + t * 4;
            pa[ks][0] = *(const uint32_t*)(pbase);
            pa[ks][1] = *(const uint32_t*)(pbase + 8 * 144);
            pa[ks][2] = *(const uint32_t*)(pbase + 16);
            pa[ks][3] = *(const uint32_t*)(pbase + 8 * 144 + 16);
        }
        #pragma unroll
        for (int nt = 0; nt < 16; ++nt) {
            int cb = khalf * 128 + nt * 8 + g;
            #pragma unroll
            for (int ks = 0; ks < 4; ++ks) {
                const char* vbase = smem + VS_OFF + (ks * 8 + t) * 1056 + cb * 4;
                uint32_t b0 = *(const uint32_t*)(vbase);
                uint32_t b1 = *(const uint32_t*)(vbase + 4 * 1056);
                mma_tf32_1688(D[nt], pa[ks][0], pa[ks][1], pa[ks][2], pa[ks][3], b0, b1);
            }
        }
        __syncthreads();
    }

    // ---- epilogue: out = x + D / l, via smem transpose, two channel halves ----
    float il0 = 1.0f / l_run0, il1 = 1.0f / l_run1;
    const float* xb = x + (size_t)b * CN * NN + m0;
    float* ob = out + (size_t)b * CN * NN + m0;
    float* Osh = (float*)(smem + OSH_OFF);    // [128][68]
    #pragma unroll
    for (int h = 0; h < 2; ++h) {
        if (khalf == h) {
            #pragma unroll
            for (int nt = 0; nt < 16; ++nt) {
                int c = nt * 8 + 2 * t;
                Osh[c * 68 + q0 + g]           = D[nt][0] * il0;
                Osh[(c + 1) * 68 + q0 + g]     = D[nt][1] * il0;
                Osh[c * 68 + q0 + 8 + g]       = D[nt][2] * il1;
                Osh[(c + 1) * 68 + q0 + 8 + g] = D[nt][3] * il1;
            }
        }
        __syncthreads();
        #pragma unroll
        for (int i = tid; i < 8192; i += 256) {
            int c = i >> 6, q = i & 63;
            size_t go = (size_t)(h * 128 + c) * NN + q;
            ob[go] = xb[go] + Osh[c * 68 + q];
        }
        __syncthreads();
    }
}

// ---------------- launcher ----------------
extern "C" void kernel_launch(void* const* d_in, const int* in_sizes, int n_in,
                              void* d_out, int out_size) {
    const float* x  = (const float*)d_in[0];
    const float* w1 = (const float*)d_in[1];
    const float* w2 = (const float*)d_in[2];
    const float* w3 = (const float*)d_in[3];
    const float* g1 = (const float*)d_in[4];
    const float* b1 = (const float*)d_in[5];
    const float* g2 = (const float*)d_in[6];
    const float* b2 = (const float*)d_in[7];
    const float* g3 = (const float*)d_in[8];
    const float* b3 = (const float*)d_in[9];
    float* out = (float*)d_out;

    cudaFuncSetAttribute(flash_mma, cudaFuncAttributeMaxDynamicSharedMemorySize, SM_TOT);

    zero_kernel<<<256, 256>>>();
    mean_kernel<<<256, 256>>>(x);
    gram_kernel<<<dim3(8, 8, 16), 256>>>(x);
    fold_kernel<<<320, 256>>>(w1, w2, w3, g1, b1, g2, b2, g3, b3);
    qkd_kernel<<<dim3(5, 64, 4), 256>>>(x);
    flash_mma<<<dim3(64, 4), 256, SM_TOT>>>(x, out);
}

// round 5
// speedup vs baseline: 2.9768x; 1.2625x over previous
#include <cuda_runtime.h>
#include <cuda_bf16.h>
#include <cstdint>

#define BB 4
#define CN 256
#define NN 4096
#define OTOT 320
#define BN_TOT 16384.0f

// ---------------- device scratch ----------------
__device__ float g_mx[CN];
__device__ float g_G[CN * CN];
__device__ float g_WfT[CN * OTOT];
__device__ float g_Bf[OTOT];
__device__ __nv_bfloat16 g_Qb[(size_t)BB * NN * 128]; // [b][n][qhi32|qlo32|qhi32|0]
__device__ __nv_bfloat16 g_Kb[(size_t)BB * NN * 128]; // [b][n][khi32|khi32|klo32|0]
__device__ __nv_bfloat16 g_Vb[(size_t)BB * CN * NN];  // bf16, [b][c][n]

// ---------------- mma.sync wrappers (base sm_103 compatible) ----------------
__device__ __forceinline__ void mma_bf16_16816(float* c, uint32_t a0, uint32_t a1,
                                               uint32_t a2, uint32_t a3,
                                               uint32_t b0, uint32_t b1) {
    asm volatile("mma.sync.aligned.m16n8k16.row.col.f32.bf16.bf16.f32 "
        "{%0,%1,%2,%3}, {%4,%5,%6,%7}, {%8,%9}, {%0,%1,%2,%3};"
        : "+f"(c[0]), "+f"(c[1]), "+f"(c[2]), "+f"(c[3])
        : "r"(a0), "r"(a1), "r"(a2), "r"(a3), "r"(b0), "r"(b1));
}
__device__ __forceinline__ uint32_t f2tf32(float f) {
    uint32_t u;
    asm("cvt.rn.tf32.f32 %0, %1;" : "=r"(u) : "f"(f));
    return u;
}
__device__ __forceinline__ void cp16(uint32_t dst, const void* src) {
    asm volatile("cp.async.cg.shared.global [%0], [%1], 16;" :: "r"(dst), "l"(src));
}
#define CP_COMMIT() asm volatile("cp.async.commit_group;" ::: "memory")
#define CP_WAIT1()  asm volatile("cp.async.wait_group 1;" ::: "memory")
__device__ __forceinline__ uint32_t smem_u32(const void* p) {
    uint32_t a;
    asm("{ .reg .u64 t; cvta.to.shared.u64 t, %1; cvt.u32.u64 %0, t; }" : "=r"(a) : "l"(p));
    return a;
}
__device__ __forceinline__ uint32_t pack_bf2(float a, float b) {
    __nv_bfloat162 h = __floats2bfloat162_rn(a, b);
    return *(uint32_t*)&h;
}

// ---------------- prologue: BN folding ----------------
__global__ void zero_kernel() { g_G[blockIdx.x * blockDim.x + threadIdx.x] = 0.0f; }

__global__ void mean_kernel(const float* __restrict__ x) {
    int c = blockIdx.x, tid = threadIdx.x;
    float s = 0.0f;
    #pragma unroll 4
    for (int i = 0; i < 64; ++i) {
        int k = tid + i * 256;
        s += x[(k >> 12) * (CN * NN) + (k & 4095) + c * NN];
    }
    __shared__ float red[256];
    red[tid] = s; __syncthreads();
    for (int st = 128; st > 0; st >>= 1) { if (tid < st) red[tid] += red[tid + st]; __syncthreads(); }
    if (tid == 0) g_mx[c] = red[0] * (1.0f / BN_TOT);
}

__global__ void gram_kernel(const float* __restrict__ x) {
    __shared__ float As[64][33], Bs[64][33];
    int c0 = blockIdx.x * 32, c1 = blockIdx.y * 32, kbase = blockIdx.z * 1024;
    int tid = threadIdx.x, ty = tid >> 4, tx = tid & 15;
    float a00 = 0, a01 = 0, a10 = 0, a11 = 0;
    for (int it = 0; it < 16; ++it) {
        int k0 = kbase + it * 64;
        #pragma unroll
        for (int r = 0; r < 8; ++r) {
            int idx = tid + r * 256, kk = idx & 63, ci = idx >> 6;
            int k = k0 + kk, off = (k >> 12) * (CN * NN) + (k & 4095);
            As[kk][ci] = x[off + (c0 + ci) * NN];
            Bs[kk][ci] = x[off + (c1 + ci) * NN];
        }
        __syncthreads();
        #pragma unroll
        for (int kk = 0; kk < 64; ++kk) {
            float x0 = As[kk][2 * ty], x1 = As[kk][2 * ty + 1];
            float y0 = Bs[kk][2 * tx], y1 = Bs[kk][2 * tx + 1];
            a00 += x0 * y0; a01 += x0 * y1; a10 += x1 * y0; a11 += x1 * y1;
        }
        __syncthreads();
    }
    atomicAdd(&g_G[(c0 + 2 * ty) * CN + c1 + 2 * tx], a00);
    atomicAdd(&g_G[(c0 + 2 * ty) * CN + c1 + 2 * tx + 1], a01);
    atomicAdd(&g_G[(c0 + 2 * ty + 1) * CN + c1 + 2 * tx], a10);
    atomicAdd(&g_G[(c0 + 2 * ty + 1) * CN + c1 + 2 * tx + 1], a11);
}

__global__ void fold_kernel(const float* __restrict__ w1, const float* __restrict__ w2,
                            const float* __restrict__ w3,
                            const float* __restrict__ g1, const float* __restrict__ b1,
                            const float* __restrict__ g2, const float* __restrict__ b2,
                            const float* __restrict__ g3, const float* __restrict__ b3) {
    int o = blockIdx.x, tid = threadIdx.x;
    const float* w; float gg, bb;
    if (o < 32)      { w = w1 + o * CN;        gg = g1[o];      bb = b1[o]; }
    else if (o < 64) { w = w2 + (o - 32) * CN; gg = g2[o - 32]; bb = b2[o - 32]; }
    else             { w = w3 + (o - 64) * CN; gg = g3[o - 64]; bb = b3[o - 64]; }
    __shared__ float ws[256], redE[256], redM[256], sc_sh;
    ws[tid] = w[tid]; __syncthreads();
    float acc = 0.0f;
    #pragma unroll 4
    for (int c = 0; c < CN; ++c) acc += g_G[c * CN + tid] * ws[c];
    redE[tid] = acc * ws[tid];
    redM[tid] = ws[tid] * g_mx[tid];
    __syncthreads();
    for (int st = 128; st > 0; st >>= 1) {
        if (tid < st) { redE[tid] += redE[tid + st]; redM[tid] += redM[tid + st]; }
        __syncthreads();
    }
    if (tid == 0) {
        float m = redM[0], E = redE[0] * (1.0f / BN_TOT);
        float rs = rsqrtf(E - m * m + 1e-5f);
        float sc = gg * rs;
        sc_sh = sc;
        g_Bf[o] = bb - sc * m;
    }
    __syncthreads();
    g_WfT[tid * OTOT + o] = sc_sh * ws[tid];
}

// ---------------- conv+relu -> Qb/Kb (bf16 hi/lo) and Vb (bf16, [b][c][n]) ----------------
__global__ void qkd_kernel(const float* __restrict__ x) {
    __shared__ float Ws[16][64], Xs[16][64];
    int o0 = blockIdx.x * 64, n0 = blockIdx.y * 64, b = blockIdx.z;
    int tid = threadIdx.x, ty = tid >> 4, tx = tid & 15;
    float acc[4][4] = {};
    const float* xb = x + (size_t)b * CN * NN;
    for (int k0 = 0; k0 < CN; k0 += 16) {
        #pragma unroll
        for (int r = 0; r < 4; ++r) {
            int idx = tid + r * 256, i = idx & 63, kk = idx >> 6;
            Ws[kk][i] = g_WfT[(k0 + kk) * OTOT + o0 + i];
            Xs[kk][i] = xb[(k0 + kk) * NN + n0 + i];
        }
        __syncthreads();
        #pragma unroll
        for (int kk = 0; kk < 16; ++kk) {
            float4 a = ((const float4*)Ws[kk])[ty];
            float4 bv = ((const float4*)Xs[kk])[tx];
            acc[0][0] += a.x*bv.x; acc[0][1] += a.x*bv.y; acc[0][2] += a.x*bv.z; acc[0][3] += a.x*bv.w;
            acc[1][0] += a.y*bv.x; acc[1][1] += a.y*bv.y; acc[1][2] += a.y*bv.z; acc[1][3] += a.y*bv.w;
            acc[2][0] += a.z*bv.x; acc[2][1] += a.z*bv.y; acc[2][2] += a.z*bv.z; acc[2][3] += a.z*bv.w;
            acc[3][0] += a.w*bv.x; acc[3][1] += a.w*bv.y; acc[3][2] += a.w*bv.z; acc[3][3] += a.w*bv.w;
        }
        __syncthreads();
    }
    __nv_bfloat16 zero = __float2bfloat16(0.0f);
    #pragma unroll
    for (int i = 0; i < 4; ++i) {
        int o = o0 + ty * 4 + i;
        float bias = g_Bf[o];
        #pragma unroll
        for (int j = 0; j < 4; ++j) {
            int n = n0 + tx * 4 + j;
            float v = fmaxf(acc[i][j] + bias, 0.0f);
            if (o >= 64) {
                g_Vb[((size_t)b * CN + (o - 64)) * NN + n] = __float2bfloat16(v);
            } else {
                __nv_bfloat16 hi = __float2bfloat16(v);
                __nv_bfloat16 lo = __float2bfloat16(v - __bfloat162float(hi));
                size_t base = ((size_t)b * NN + n) * 128;
                if (o < 32) {
                    g_Qb[base + o] = hi; g_Qb[base + 32 + o] = lo;
                    g_Qb[base + 64 + o] = hi; g_Qb[base + 96 + o] = zero;
                } else {
                    int oc = o - 32;
                    g_Kb[base + oc] = hi; g_Kb[base + 32 + oc] = hi;
                    g_Kb[base + 64 + oc] = lo; g_Kb[base + 96 + oc] = zero;
                }
            }
        }
    }
}

// ---------------- flash attention via mma.sync, cp.async double-buffered ----------------
// Block 256 thr (8 warps), 64 queries. Warp = (mrow = wid&3) x (khalf = wid>>2).
// SMEM: Ks 2x[32][272B]@0 (17408), Vs 2x[256c][80B]@17408 (40960),
//       Ps [64][80B]@58368 (5120), stM@63488 (512), stL@64000 (512) -> 64512
#define KS_OFF 0
#define KS_BUF 8704
#define VS_OFF 17408
#define VS_BUF 20480
#define PS_OFF 58368
#define STM_OFF 63488
#define STL_OFF 64000
#define SM_TOT 64512
#define OSH_OFF VS_OFF   // epilogue reuse: [128][68] f32 = 34816 bytes

__global__ void __launch_bounds__(256, 2)
flash_mma(const float* __restrict__ x, float* __restrict__ out) {
    extern __shared__ __align__(16) char smem[];
    uint32_t sb = smem_u32(smem);
    int tid = threadIdx.x;
    int lane = tid & 31, wid = tid >> 5;
    int g = lane >> 2, t = lane & 3;
    int mrow = wid & 3, khalf = wid >> 2;
    int q0 = mrow * 16;
    int b = blockIdx.y, m0 = blockIdx.x * 64;

    float* stM = (float*)(smem + STM_OFF);
    float* stL = (float*)(smem + STL_OFF);

    // ---- Q fragments register-resident (96-dim hi/lo packing, 6 ksteps) ----
    uint32_t qa[6][4];
    {
        const __nv_bfloat16* qr0 = g_Qb + ((size_t)b * NN + m0 + q0 + g) * 128;
        const __nv_bfloat16* qr1 = qr0 + (size_t)8 * 128;
        #pragma unroll
        for (int ks = 0; ks < 6; ++ks) {
            int e = ks * 16 + 2 * t;
            qa[ks][0] = *(const uint32_t*)(qr0 + e);
            qa[ks][1] = *(const uint32_t*)(qr1 + e);
            qa[ks][2] = *(const uint32_t*)(qr0 + e + 8);
            qa[ks][3] = *(const uint32_t*)(qr1 + e + 8);
        }
    }

    const char* kgb = (const char*)(g_Kb + ((size_t)b * NN) * 128);
    const char* vgb = (const char*)(g_Vb + (size_t)b * CN * NN);

    // prefetch chunk 0 into buf 0
    {
        #pragma unroll
        for (int i = tid; i < 512; i += 256) {
            int row = i >> 4, col = i & 15;
            cp16(sb + KS_OFF + row * 272 + col * 16, kgb + (size_t)row * 256 + col * 16);
        }
        #pragma unroll
        for (int i = tid; i < 1024; i += 256) {
            int c = i >> 2, j = i & 3;
            cp16(sb + VS_OFF + c * 80 + j * 16, vgb + (size_t)c * (NN * 2) + j * 16);
        }
        CP_COMMIT();
    }

    float D[16][4];
    #pragma unroll
    for (int nt = 0; nt < 16; ++nt) { D[nt][0] = D[nt][1] = D[nt][2] = D[nt][3] = 0.0f; }
    float m_run0 = -1e30f, m_run1 = -1e30f, l_run0 = 0.0f, l_run1 = 0.0f;

    for (int ch = 0; ch < 128; ++ch) {
        int buf = ch & 1;
        __syncthreads();   // B1: prev chunk's consumers done with buf^1 + Ps
        // prefetch ch+1 into buf^1
        if (ch + 1 < 128) {
            int n1 = (ch + 1) * 32;
            uint32_t kd = sb + KS_OFF + (buf ^ 1) * KS_BUF;
            uint32_t vd = sb + VS_OFF + (buf ^ 1) * VS_BUF;
            #pragma unroll
            for (int i = tid; i < 512; i += 256) {
                int row = i >> 4, col = i & 15;
                cp16(kd + row * 272 + col * 16, kgb + (size_t)(n1 + row) * 256 + col * 16);
            }
            #pragma unroll
            for (int i = tid; i < 1024; i += 256) {
                int c = i >> 2, j = i & 3;
                cp16(vd + c * 80 + j * 16, vgb + (size_t)c * (NN * 2) + (size_t)n1 * 2 + j * 16);
            }
        }
        CP_COMMIT();
        CP_WAIT1();
        __syncthreads();   // B2: buf data visible to all

        // ---- QK^T: 16 q x 16 keys (khalf), k=96 (6 ksteps) ----
        const char* ksm = smem + KS_OFF + buf * KS_BUF;
        float sc[2][4] = {};
        #pragma unroll
        for (int ks = 0; ks < 6; ++ks) {
            #pragma unroll
            for (int nt = 0; nt < 2; ++nt) {
                const char* kbase = ksm + (khalf * 16 + nt * 8 + g) * 272 + ks * 32 + t * 4;
                uint32_t b0 = *(const uint32_t*)(kbase);
                uint32_t b1 = *(const uint32_t*)(kbase + 16);
                mma_bf16_16816(sc[nt], qa[ks][0], qa[ks][1], qa[ks][2], qa[ks][3], b0, b1);
            }
        }
        // partial row max over this warp's 16 keys
        float mp0 = fmaxf(fmaxf(sc[0][0], sc[0][1]), fmaxf(sc[1][0], sc[1][1]));
        float mp1 = fmaxf(fmaxf(sc[0][2], sc[0][3]), fmaxf(sc[1][2], sc[1][3]));
        mp0 = fmaxf(mp0, __shfl_xor_sync(0xffffffffu, mp0, 1));
        mp0 = fmaxf(mp0, __shfl_xor_sync(0xffffffffu, mp0, 2));
        mp1 = fmaxf(mp1, __shfl_xor_sync(0xffffffffu, mp1, 1));
        mp1 = fmaxf(mp1, __shfl_xor_sync(0xffffffffu, mp1, 2));
        if (t == 0) {
            stM[khalf * 64 + q0 + g] = mp0;
            stM[khalf * 64 + q0 + 8 + g] = mp1;
        }
        __syncthreads();   // B3: stM visible
        float mt0 = fmaxf(stM[q0 + g], stM[64 + q0 + g]);
        float mt1 = fmaxf(stM[q0 + 8 + g], stM[64 + q0 + 8 + g]);
        float mn0 = fmaxf(m_run0, mt0), mn1 = fmaxf(m_run1, mt1);
        float f0 = __expf(m_run0 - mn0), f1 = __expf(m_run1 - mn1);
        m_run0 = mn0; m_run1 = mn1;

        float e00 = __expf(sc[0][0] - mn0), e01 = __expf(sc[0][1] - mn0);
        float e02 = __expf(sc[0][2] - mn1), e03 = __expf(sc[0][3] - mn1);
        float e10 = __expf(sc[1][0] - mn0), e11 = __expf(sc[1][1] - mn0);
        float e12 = __expf(sc[1][2] - mn1), e13 = __expf(sc[1][3] - mn1);
        float ls0 = e00 + e01 + e10 + e11;
        float ls1 = e02 + e03 + e12 + e13;

        // own-half PV A-frags straight from registers (kstep = khalf)
        uint32_t paA[2][4];
        paA[khalf][0] = pack_bf2(e00, e01);
        paA[khalf][1] = pack_bf2(e02, e03);
        paA[khalf][2] = pack_bf2(e10, e11);
        paA[khalf][3] = pack_bf2(e12, e13);
        // publish own half to Ps (bf16, [64 q][40])
        {
            char* pr0 = smem + PS_OFF + (q0 + g) * 80 + (khalf * 16 + 2 * t) * 2;
            char* pr1 = smem + PS_OFF + (q0 + 8 + g) * 80 + (khalf * 16 + 2 * t) * 2;
            *(uint32_t*)(pr0)      = paA[khalf][0];
            *(uint32_t*)(pr0 + 16) = paA[khalf][2];
            *(uint32_t*)(pr1)      = paA[khalf][1];
            *(uint32_t*)(pr1 + 16) = paA[khalf][3];
        }
        ls0 += __shfl_xor_sync(0xffffffffu, ls0, 1);
        ls0 += __shfl_xor_sync(0xffffffffu, ls0, 2);
        ls1 += __shfl_xor_sync(0xffffffffu, ls1, 1);
        ls1 += __shfl_xor_sync(0xffffffffu, ls1, 2);
        if (t == 0) {
            stL[khalf * 64 + q0 + g] = ls0;
            stL[khalf * 64 + q0 + 8 + g] = ls1;
        }
        // rescale accumulators while Ps propagates
        #pragma unroll
        for (int nt = 0; nt < 16; ++nt) {
            D[nt][0] *= f0; D[nt][1] *= f0;
            D[nt][2] *= f1; D[nt][3] *= f1;
        }
        __syncthreads();   // B4: Ps + stL visible
        l_run0 = l_run0 * f0 + stL[q0 + g] + stL[64 + q0 + g];
        l_run1 = l_run1 * f1 + stL[q0 + 8 + g] + stL[64 + q0 + 8 + g];

        // other-half A-frags from Ps
        {
            int oh = khalf ^ 1;
            const char* pb0 = smem + PS_OFF + (q0 + g) * 80 + (oh * 16 + 2 * t) * 2;
            const char* pb1 = smem + PS_OFF + (q0 + 8 + g) * 80 + (oh * 16 + 2 * t) * 2;
            paA[oh][0] = *(const uint32_t*)(pb0);
            paA[oh][1] = *(const uint32_t*)(pb1);
            paA[oh][2] = *(const uint32_t*)(pb0 + 16);
            paA[oh][3] = *(const uint32_t*)(pb1 + 16);
        }

        // ---- PV: D[16q][128c] += P[16q][32k] * V[32k][128c], bf16 m16n8k16 ----
        const char* vsm = smem + VS_OFF + buf * VS_BUF;
        #pragma unroll
        for (int nt = 0; nt < 16; ++nt) {
            const char* vb = vsm + (khalf * 128 + nt * 8 + g) * 80 + t * 4;
            #pragma unroll
            for (int ks2 = 0; ks2 < 2; ++ks2) {
                uint32_t b0 = *(const uint32_t*)(vb + ks2 * 32);
                uint32_t b1 = *(const uint32_t*)(vb + ks2 * 32 + 16);
                mma_bf16_16816(D[nt], paA[ks2][0], paA[ks2][1], paA[ks2][2], paA[ks2][3], b0, b1);
            }
        }
    }
    __syncthreads();

    // ---- epilogue: out = x + D/l via smem transpose, two channel halves ----
    float il0 = 1.0f / l_run0, il1 = 1.0f / l_run1;
    const float* xb = x + (size_t)b * CN * NN + m0;
    float* ob = out + (size_t)b * CN * NN + m0;
    float* Osh = (float*)(smem + OSH_OFF);    // [128][68]
    #pragma unroll
    for (int h = 0; h < 2; ++h) {
        if (khalf == h) {
            #pragma unroll
            for (int nt = 0; nt < 16; ++nt) {
                int c = nt * 8 + 2 * t;
                Osh[c * 68 + q0 + g]           = D[nt][0] * il0;
                Osh[(c + 1) * 68 + q0 + g]     = D[nt][1] * il0;
                Osh[c * 68 + q0 + 8 + g]       = D[nt][2] * il1;
                Osh[(c + 1) * 68 + q0 + 8 + g] = D[nt][3] * il1;
            }
        }
        __syncthreads();
        #pragma unroll
        for (int i = tid; i < 8192; i += 256) {
            int c = i >> 6, q = i & 63;
            size_t go = (size_t)(h * 128 + c) * NN + q;
            ob[go] = xb[go] + Osh[c * 68 + q];
        }
        __syncthreads();
    }
}

// ---------------- launcher ----------------
extern "C" void kernel_launch(void* const* d_in, const int* in_sizes, int n_in,
                              void* d_out, int out_size) {
    const float* x  = (const float*)d_in[0];
    const float* w1 = (const float*)d_in[1];
    const float* w2 = (const float*)d_in[2];
    const float* w3 = (const float*)d_in[3];
    const float* g1 = (const float*)d_in[4];
    const float* b1 = (const float*)d_in[5];
    const float* g2 = (const float*)d_in[6];
    const float* b2 = (const float*)d_in[7];
    const float* g3 = (const float*)d_in[8];
    const float* b3 = (const float*)d_in[9];
    float* out = (float*)d_out;

    cudaFuncSetAttribute(flash_mma, cudaFuncAttributeMaxDynamicSharedMemorySize, SM_TOT);

    zero_kernel<<<256, 256>>>();
    mean_kernel<<<256, 256>>>(x);
    gram_kernel<<<dim3(8, 8, 16), 256>>>(x);
    fold_kernel<<<320, 256>>>(w1, w2, w3, g1, b1, g2, b2, g3, b3);
    qkd_kernel<<<dim3(5, 64, 4), 256>>>(x);
    flash_mma<<<dim3(64, 4), 256, SM_TOT>>>(x, out);
}

// round 6
// speedup vs baseline: 3.4292x; 1.1520x over previous
#include <cuda_runtime.h>
#include <cuda_bf16.h>
#include <cstdint>

#define BB 4
#define CN 256
#define NN 4096
#define OTOT 320
#define BN_TOT 16384.0f
#define KTOT 16384

// ---------------- device scratch ----------------
__device__ float g_mx[CN];
__device__ float g_G[CN * CN];
__device__ float g_WfT[CN * OTOT];
__device__ float g_Bf[OTOT];
__device__ __nv_bfloat16 g_xh[(size_t)CN * KTOT];     // x hi, [c][b*n]
__device__ __nv_bfloat16 g_xl[(size_t)CN * KTOT];     // x lo, [c][b*n]
__device__ __nv_bfloat16 g_Qb[(size_t)BB * NN * 128]; // [b][n][qhi32|qlo32|qhi32|0]
__device__ __nv_bfloat16 g_Kb[(size_t)BB * NN * 128]; // [b][n][khi32|khi32|klo32|0]
__device__ __nv_bfloat16 g_Vb[(size_t)BB * CN * NN];  // bf16, [b][c][n]

// ---------------- mma.sync / async helpers (base sm_103 compatible) ----------------
__device__ __forceinline__ void mma_bf16_16816(float* c, uint32_t a0, uint32_t a1,
                                               uint32_t a2, uint32_t a3,
                                               uint32_t b0, uint32_t b1) {
    asm volatile("mma.sync.aligned.m16n8k16.row.col.f32.bf16.bf16.f32 "
        "{%0,%1,%2,%3}, {%4,%5,%6,%7}, {%8,%9}, {%0,%1,%2,%3};"
        : "+f"(c[0]), "+f"(c[1]), "+f"(c[2]), "+f"(c[3])
        : "r"(a0), "r"(a1), "r"(a2), "r"(a3), "r"(b0), "r"(b1));
}
__device__ __forceinline__ void cp16(uint32_t dst, const void* src) {
    asm volatile("cp.async.cg.shared.global [%0], [%1], 16;" :: "r"(dst), "l"(src));
}
#define CP_COMMIT() asm volatile("cp.async.commit_group;" ::: "memory")
#define CP_WAIT0()  asm volatile("cp.async.wait_group 0;" ::: "memory")
#define CP_WAIT1()  asm volatile("cp.async.wait_group 1;" ::: "memory")
__device__ __forceinline__ uint32_t smem_u32(const void* p) {
    uint32_t a;
    asm("{ .reg .u64 t; cvta.to.shared.u64 t, %1; cvt.u32.u64 %0, t; }" : "=r"(a) : "l"(p));
    return a;
}
__device__ __forceinline__ uint32_t pack_bf2(float a, float b) {
    __nv_bfloat162 h = __floats2bfloat162_rn(a, b);
    return *(uint32_t*)&h;
}

// ---------------- prologue ----------------
__global__ void zero_kernel() { g_G[blockIdx.x * blockDim.x + threadIdx.x] = 0.0f; }

// split x into bf16 hi/lo, layout [c][b*4096+n]
__global__ void convx_kernel(const float* __restrict__ x) {
    int bc = blockIdx.x;                 // 1024 = b*256 + c
    int b = bc >> 8, c = bc & 255;
    const float* src = x + ((size_t)b * CN + c) * NN;
    __nv_bfloat16* dh = g_xh + (size_t)c * KTOT + b * NN;
    __nv_bfloat16* dl = g_xl + (size_t)c * KTOT + b * NN;
    int tid = threadIdx.x;
    #pragma unroll
    for (int i = 0; i < 16; ++i) {
        int idx = tid + i * 256;
        float v = src[idx];
        __nv_bfloat16 hi = __float2bfloat16(v);
        __nv_bfloat16 lo = __float2bfloat16(v - __bfloat162float(hi));
        dh[idx] = hi; dl[idx] = lo;
    }
}

__global__ void mean_kernel(const float* __restrict__ x) {
    int c = blockIdx.x, tid = threadIdx.x;
    float s = 0.0f;
    #pragma unroll 4
    for (int i = 0; i < 64; ++i) {
        int k = tid + i * 256;
        s += x[(k >> 12) * (CN * NN) + (k & 4095) + c * NN];
    }
    __shared__ float red[256];
    red[tid] = s; __syncthreads();
    for (int st = 128; st > 0; st >>= 1) { if (tid < st) red[tid] += red[tid + st]; __syncthreads(); }
    if (tid == 0) g_mx[c] = red[0] * (1.0f / BN_TOT);
}

// ---------------- Gram via mma.sync (hi/lo bf16 compensation) ----------------
// grid (4,4,16): 64x64 c-tile, k-segment 1024. 8 warps = 2(m) x 4(n), warp tile 32x16.
// smem rows padded to 72 bf16 (144B): frag word idx = 4*row + t (mod 32) conflict-free.
#define GR_STRIDE 144
#define GR_MAT (64 * GR_STRIDE)
__global__ void __launch_bounds__(256, 2)
gram_mma(int dummy) {
    __shared__ __align__(16) char smem[4 * GR_MAT];   // Ah, Al, Bh, Bl
    uint32_t sb = smem_u32(smem);
    int tid = threadIdx.x;
    int lane = tid & 31, wid = tid >> 5;
    int g = lane >> 2, t = lane & 3;
    int wm = wid >> 2, wn = wid & 3;
    int c0 = blockIdx.x * 64, c1 = blockIdx.y * 64;
    int kseg = blockIdx.z * 1024;

    float C[2][2][4] = {};

    for (int ch = 0; ch < 16; ++ch) {
        int k0 = kseg + ch * 64;
        __syncthreads();
        // stage Ah/Al (rows c0..) and Bh/Bl (rows c1..): 4 matrices x 512 cp16
        #pragma unroll
        for (int i = tid; i < 512; i += 256) {
            int row = i >> 3, col = i & 7;
            cp16(sb + 0 * GR_MAT + row * GR_STRIDE + col * 16,
                 g_xh + (size_t)(c0 + row) * KTOT + k0 + col * 8);
            cp16(sb + 1 * GR_MAT + row * GR_STRIDE + col * 16,
                 g_xl + (size_t)(c0 + row) * KTOT + k0 + col * 8);
            cp16(sb + 2 * GR_MAT + row * GR_STRIDE + col * 16,
                 g_xh + (size_t)(c1 + row) * KTOT + k0 + col * 8);
            cp16(sb + 3 * GR_MAT + row * GR_STRIDE + col * 16,
                 g_xl + (size_t)(c1 + row) * KTOT + k0 + col * 8);
        }
        CP_COMMIT();
        CP_WAIT0();
        __syncthreads();
        const char* Ah = smem;
        const char* Al = smem + GR_MAT;
        const char* Bh = smem + 2 * GR_MAT;
        const char* Bl = smem + 3 * GR_MAT;
        #pragma unroll
        for (int ks = 0; ks < 4; ++ks) {
            int koff = ks * 32 + t * 4;
            uint32_t ah[2][4], al[2][4];
            #pragma unroll
            for (int fm = 0; fm < 2; ++fm) {
                int r = wm * 32 + fm * 16 + g;
                ah[fm][0] = *(const uint32_t*)(Ah + r * GR_STRIDE + koff);
                ah[fm][1] = *(const uint32_t*)(Ah + (r + 8) * GR_STRIDE + koff);
                ah[fm][2] = *(const uint32_t*)(Ah + r * GR_STRIDE + koff + 16);
                ah[fm][3] = *(const uint32_t*)(Ah + (r + 8) * GR_STRIDE + koff + 16);
                al[fm][0] = *(const uint32_t*)(Al + r * GR_STRIDE + koff);
                al[fm][1] = *(const uint32_t*)(Al + (r + 8) * GR_STRIDE + koff);
                al[fm][2] = *(const uint32_t*)(Al + r * GR_STRIDE + koff + 16);
                al[fm][3] = *(const uint32_t*)(Al + (r + 8) * GR_STRIDE + koff + 16);
            }
            #pragma unroll
            for (int fn = 0; fn < 2; ++fn) {
                int r = wn * 16 + fn * 8 + g;
                uint32_t bh0 = *(const uint32_t*)(Bh + r * GR_STRIDE + koff);
                uint32_t bh1 = *(const uint32_t*)(Bh + r * GR_STRIDE + koff + 16);
                uint32_t bl0 = *(const uint32_t*)(Bl + r * GR_STRIDE + koff);
                uint32_t bl1 = *(const uint32_t*)(Bl + r * GR_STRIDE + koff + 16);
                #pragma unroll
                for (int fm = 0; fm < 2; ++fm) {
                    mma_bf16_16816(C[fm][fn], ah[fm][0], ah[fm][1], ah[fm][2], ah[fm][3], bh0, bh1);
                    mma_bf16_16816(C[fm][fn], ah[fm][0], ah[fm][1], ah[fm][2], ah[fm][3], bl0, bl1);
                    mma_bf16_16816(C[fm][fn], al[fm][0], al[fm][1], al[fm][2], al[fm][3], bh0, bh1);
                }
            }
        }
    }
    // epilogue: atomic accumulate
    #pragma unroll
    for (int fm = 0; fm < 2; ++fm) {
        #pragma unroll
        for (int fn = 0; fn < 2; ++fn) {
            int r0 = c0 + wm * 32 + fm * 16 + g;
            int cc = c1 + wn * 16 + fn * 8 + 2 * t;
            atomicAdd(&g_G[r0 * CN + cc],           C[fm][fn][0]);
            atomicAdd(&g_G[r0 * CN + cc + 1],       C[fm][fn][1]);
            atomicAdd(&g_G[(r0 + 8) * CN + cc],     C[fm][fn][2]);
            atomicAdd(&g_G[(r0 + 8) * CN + cc + 1], C[fm][fn][3]);
        }
    }
}

__global__ void fold_kernel(const float* __restrict__ w1, const float* __restrict__ w2,
                            const float* __restrict__ w3,
                            const float* __restrict__ g1, const float* __restrict__ b1,
                            const float* __restrict__ g2, const float* __restrict__ b2,
                            const float* __restrict__ g3, const float* __restrict__ b3) {
    int o = blockIdx.x, tid = threadIdx.x;
    const float* w; float gg, bb;
    if (o < 32)      { w = w1 + o * CN;        gg = g1[o];      bb = b1[o]; }
    else if (o < 64) { w = w2 + (o - 32) * CN; gg = g2[o - 32]; bb = b2[o - 32]; }
    else             { w = w3 + (o - 64) * CN; gg = g3[o - 64]; bb = b3[o - 64]; }
    __shared__ float ws[256], redE[256], redM[256], sc_sh;
    ws[tid] = w[tid]; __syncthreads();
    float acc = 0.0f;
    #pragma unroll 4
    for (int c = 0; c < CN; ++c) acc += g_G[c * CN + tid] * ws[c];
    redE[tid] = acc * ws[tid];
    redM[tid] = ws[tid] * g_mx[tid];
    __syncthreads();
    for (int st = 128; st > 0; st >>= 1) {
        if (tid < st) { redE[tid] += redE[tid + st]; redM[tid] += redM[tid + st]; }
        __syncthreads();
    }
    if (tid == 0) {
        float m = redM[0], E = redE[0] * (1.0f / BN_TOT);
        float rs = rsqrtf(E - m * m + 1e-5f);
        float sc = gg * rs;
        sc_sh = sc;
        g_Bf[o] = bb - sc * m;
    }
    __syncthreads();
    g_WfT[tid * OTOT + o] = sc_sh * ws[tid];
}

// ---------------- conv+relu -> Qb/Kb (bf16 hi/lo) and Vb (bf16, [b][c][n]) ----------------
__global__ void qkd_kernel(const float* __restrict__ x) {
    __shared__ float Ws[16][64], Xs[16][64];
    int o0 = blockIdx.x * 64, n0 = blockIdx.y * 64, b = blockIdx.z;
    int tid = threadIdx.x, ty = tid >> 4, tx = tid & 15;
    float acc[4][4] = {};
    const float* xb = x + (size_t)b * CN * NN;
    for (int k0 = 0; k0 < CN; k0 += 16) {
        #pragma unroll
        for (int r = 0; r < 4; ++r) {
            int idx = tid + r * 256, i = idx & 63, kk = idx >> 6;
            Ws[kk][i] = g_WfT[(k0 + kk) * OTOT + o0 + i];
            Xs[kk][i] = xb[(k0 + kk) * NN + n0 + i];
        }
        __syncthreads();
        #pragma unroll
        for (int kk = 0; kk < 16; ++kk) {
            float4 a = ((const float4*)Ws[kk])[ty];
            float4 bv = ((const float4*)Xs[kk])[tx];
            acc[0][0] += a.x*bv.x; acc[0][1] += a.x*bv.y; acc[0][2] += a.x*bv.z; acc[0][3] += a.x*bv.w;
            acc[1][0] += a.y*bv.x; acc[1][1] += a.y*bv.y; acc[1][2] += a.y*bv.z; acc[1][3] += a.y*bv.w;
            acc[2][0] += a.z*bv.x; acc[2][1] += a.z*bv.y; acc[2][2] += a.z*bv.z; acc[2][3] += a.z*bv.w;
            acc[3][0] += a.w*bv.x; acc[3][1] += a.w*bv.y; acc[3][2] += a.w*bv.z; acc[3][3] += a.w*bv.w;
        }
        __syncthreads();
    }
    __nv_bfloat16 zero = __float2bfloat16(0.0f);
    #pragma unroll
    for (int i = 0; i < 4; ++i) {
        int o = o0 + ty * 4 + i;
        float bias = g_Bf[o];
        #pragma unroll
        for (int j = 0; j < 4; ++j) {
            int n = n0 + tx * 4 + j;
            float v = fmaxf(acc[i][j] + bias, 0.0f);
            if (o >= 64) {
                g_Vb[((size_t)b * CN + (o - 64)) * NN + n] = __float2bfloat16(v);
            } else {
                __nv_bfloat16 hi = __float2bfloat16(v);
                __nv_bfloat16 lo = __float2bfloat16(v - __bfloat162float(hi));
                size_t base = ((size_t)b * NN + n) * 128;
                if (o < 32) {
                    g_Qb[base + o] = hi; g_Qb[base + 32 + o] = lo;
                    g_Qb[base + 64 + o] = hi; g_Qb[base + 96 + o] = zero;
                } else {
                    int oc = o - 32;
                    g_Kb[base + oc] = hi; g_Kb[base + 32 + oc] = hi;
                    g_Kb[base + 64 + oc] = lo; g_Kb[base + 96 + oc] = zero;
                }
            }
        }
    }
}

// ---------------- flash attention via mma.sync, cp.async double-buffered ----------------
#define KS_OFF 0
#define KS_BUF 8704
#define VS_OFF 17408
#define VS_BUF 20480
#define PS_OFF 58368
#define STM_OFF 63488
#define STL_OFF 64000
#define SM_TOT 64512
#define OSH_OFF VS_OFF

__global__ void __launch_bounds__(256, 2)
flash_mma(const float* __restrict__ x, float* __restrict__ out) {
    extern __shared__ __align__(16) char smem[];
    uint32_t sb = smem_u32(smem);
    int tid = threadIdx.x;
    int lane = tid & 31, wid = tid >> 5;
    int g = lane >> 2, t = lane & 3;
    int mrow = wid & 3, khalf = wid >> 2;
    int q0 = mrow * 16;
    int b = blockIdx.y, m0 = blockIdx.x * 64;

    float* stM = (float*)(smem + STM_OFF);
    float* stL = (float*)(smem + STL_OFF);

    uint32_t qa[6][4];
    {
        const __nv_bfloat16* qr0 = g_Qb + ((size_t)b * NN + m0 + q0 + g) * 128;
        const __nv_bfloat16* qr1 = qr0 + (size_t)8 * 128;
        #pragma unroll
        for (int ks = 0; ks < 6; ++ks) {
            int e = ks * 16 + 2 * t;
            qa[ks][0] = *(const uint32_t*)(qr0 + e);
            qa[ks][1] = *(const uint32_t*)(qr1 + e);
            qa[ks][2] = *(const uint32_t*)(qr0 + e + 8);
            qa[ks][3] = *(const uint32_t*)(qr1 + e + 8);
        }
    }

    const char* kgb = (const char*)(g_Kb + ((size_t)b * NN) * 128);
    const char* vgb = (const char*)(g_Vb + (size_t)b * CN * NN);

    {
        #pragma unroll
        for (int i = tid; i < 512; i += 256) {
            int row = i >> 4, col = i & 15;
            cp16(sb + KS_OFF + row * 272 + col * 16, kgb + (size_t)row * 256 + col * 16);
        }
        #pragma unroll
        for (int i = tid; i < 1024; i += 256) {
            int c = i >> 2, j = i & 3;
            cp16(sb + VS_OFF + c * 80 + j * 16, vgb + (size_t)c * (NN * 2) + j * 16);
        }
        CP_COMMIT();
    }

    float D[16][4];
    #pragma unroll
    for (int nt = 0; nt < 16; ++nt) { D[nt][0] = D[nt][1] = D[nt][2] = D[nt][3] = 0.0f; }
    float m_run0 = -1e30f, m_run1 = -1e30f, l_run0 = 0.0f, l_run1 = 0.0f;

    for (int ch = 0; ch < 128; ++ch) {
        int buf = ch & 1;
        __syncthreads();
        if (ch + 1 < 128) {
            int n1 = (ch + 1) * 32;
            uint32_t kd = sb + KS_OFF + (buf ^ 1) * KS_BUF;
            uint32_t vd = sb + VS_OFF + (buf ^ 1) * VS_BUF;
            #pragma unroll
            for (int i = tid; i < 512; i += 256) {
                int row = i >> 4, col = i & 15;
                cp16(kd + row * 272 + col * 16, kgb + (size_t)(n1 + row) * 256 + col * 16);
            }
            #pragma unroll
            for (int i = tid; i < 1024; i += 256) {
                int c = i >> 2, j = i & 3;
                cp16(vd + c * 80 + j * 16, vgb + (size_t)c * (NN * 2) + (size_t)n1 * 2 + j * 16);
            }
        }
        CP_COMMIT();
        CP_WAIT1();
        __syncthreads();

        const char* ksm = smem + KS_OFF + buf * KS_BUF;
        float sc[2][4] = {};
        #pragma unroll
        for (int ks = 0; ks < 6; ++ks) {
            #pragma unroll
            for (int nt = 0; nt < 2; ++nt) {
                const char* kbase = ksm + (khalf * 16 + nt * 8 + g) * 272 + ks * 32 + t * 4;
                uint32_t b0 = *(const uint32_t*)(kbase);
                uint32_t b1 = *(const uint32_t*)(kbase + 16);
                mma_bf16_16816(sc[nt], qa[ks][0], qa[ks][1], qa[ks][2], qa[ks][3], b0, b1);
            }
        }
        float mp0 = fmaxf(fmaxf(sc[0][0], sc[0][1]), fmaxf(sc[1][0], sc[1][1]));
        float mp1 = fmaxf(fmaxf(sc[0][2], sc[0][3]), fmaxf(sc[1][2], sc[1][3]));
        mp0 = fmaxf(mp0, __shfl_xor_sync(0xffffffffu, mp0, 1));
        mp0 = fmaxf(mp0, __shfl_xor_sync(0xffffffffu, mp0, 2));
        mp1 = fmaxf(mp1, __shfl_xor_sync(0xffffffffu, mp1, 1));
        mp1 = fmaxf(mp1, __shfl_xor_sync(0xffffffffu, mp1, 2));
        if (t == 0) {
            stM[khalf * 64 + q0 + g] = mp0;
            stM[khalf * 64 + q0 + 8 + g] = mp1;
        }
        __syncthreads();
        float mt0 = fmaxf(stM[q0 + g], stM[64 + q0 + g]);
        float mt1 = fmaxf(stM[q0 + 8 + g], stM[64 + q0 + 8 + g]);
        float mn0 = fmaxf(m_run0, mt0), mn1 = fmaxf(m_run1, mt1);
        float f0 = __expf(m_run0 - mn0), f1 = __expf(m_run1 - mn1);
        m_run0 = mn0; m_run1 = mn1;

        float e00 = __expf(sc[0][0] - mn0), e01 = __expf(sc[0][1] - mn0);
        float e02 = __expf(sc[0][2] - mn1), e03 = __expf(sc[0][3] - mn1);
        float e10 = __expf(sc[1][0] - mn0), e11 = __expf(sc[1][1] - mn0);
        float e12 = __expf(sc[1][2] - mn1), e13 = __expf(sc[1][3] - mn1);
        float ls0 = e00 + e01 + e10 + e11;
        float ls1 = e02 + e03 + e12 + e13;

        uint32_t paA[2][4];
        paA[khalf][0] = pack_bf2(e00, e01);
        paA[khalf][1] = pack_bf2(e02, e03);
        paA[khalf][2] = pack_bf2(e10, e11);
        paA[khalf][3] = pack_bf2(e12, e13);
        {
            char* pr0 = smem + PS_OFF + (q0 + g) * 80 + (khalf * 16 + 2 * t) * 2;
            char* pr1 = smem + PS_OFF + (q0 + 8 + g) * 80 + (khalf * 16 + 2 * t) * 2;
            *(uint32_t*)(pr0)      = paA[khalf][0];
            *(uint32_t*)(pr0 + 16) = paA[khalf][2];
            *(uint32_t*)(pr1)      = paA[khalf][1];
            *(uint32_t*)(pr1 + 16) = paA[khalf][3];
        }
        ls0 += __shfl_xor_sync(0xffffffffu, ls0, 1);
        ls0 += __shfl_xor_sync(0xffffffffu, ls0, 2);
        ls1 += __shfl_xor_sync(0xffffffffu, ls1, 1);
        ls1 += __shfl_xor_sync(0xffffffffu, ls1, 2);
        if (t == 0) {
            stL[khalf * 64 + q0 + g] = ls0;
            stL[khalf * 64 + q0 + 8 + g] = ls1;
        }
        // ballot-guarded rescale: skipped once the running max stabilizes
        uint32_t need = __ballot_sync(0xffffffffu, (f0 < 1.0f) || (f1 < 1.0f));
        if (need) {
            #pragma unroll
            for (int nt = 0; nt < 16; ++nt) {
                D[nt][0] *= f0; D[nt][1] *= f0;
                D[nt][2] *= f1; D[nt][3] *= f1;
            }
        }
        __syncthreads();
        l_run0 = l_run0 * f0 + stL[q0 + g] + stL[64 + q0 + g];
        l_run1 = l_run1 * f1 + stL[q0 + 8 + g] + stL[64 + q0 + 8 + g];

        {
            int oh = khalf ^ 1;
            const char* pb0 = smem + PS_OFF + (q0 + g) * 80 + (oh * 16 + 2 * t) * 2;
            const char* pb1 = smem + PS_OFF + (q0 + 8 + g) * 80 + (oh * 16 + 2 * t) * 2;
            paA[oh][0] = *(const uint32_t*)(pb0);
            paA[oh][1] = *(const uint32_t*)(pb1);
            paA[oh][2] = *(const uint32_t*)(pb0 + 16);
            paA[oh][3] = *(const uint32_t*)(pb1 + 16);
        }

        const char* vsm = smem + VS_OFF + buf * VS_BUF;
        #pragma unroll
        for (int nt = 0; nt < 16; ++nt) {
            const char* vb = vsm + (khalf * 128 + nt * 8 + g) * 80 + t * 4;
            #pragma unroll
            for (int ks2 = 0; ks2 < 2; ++ks2) {
                uint32_t b0 = *(const uint32_t*)(vb + ks2 * 32);
                uint32_t b1 = *(const uint32_t*)(vb + ks2 * 32 + 16);
                mma_bf16_16816(D[nt], paA[ks2][0], paA[ks2][1], paA[ks2][2], paA[ks2][3], b0, b1);
            }
        }
    }
    __syncthreads();

    float il0 = 1.0f / l_run0, il1 = 1.0f / l_run1;
    const float* xb = x + (size_t)b * CN * NN + m0;
    float* ob = out + (size_t)b * CN * NN + m0;
    float* Osh = (float*)(smem + OSH_OFF);
    #pragma unroll
    for (int h = 0; h < 2; ++h) {
        if (khalf == h) {
            #pragma unroll
            for (int nt = 0; nt < 16; ++nt) {
                int c = nt * 8 + 2 * t;
                Osh[c * 68 + q0 + g]           = D[nt][0] * il0;
                Osh[(c + 1) * 68 + q0 + g]     = D[nt][1] * il0;
                Osh[c * 68 + q0 + 8 + g]       = D[nt][2] * il1;
                Osh[(c + 1) * 68 + q0 + 8 + g] = D[nt][3] * il1;
            }
        }
        __syncthreads();
        #pragma unroll
        for (int i = tid; i < 8192; i += 256) {
            int c = i >> 6, q = i & 63;
            size_t go = (size_t)(h * 128 + c) * NN + q;
            ob[go] = xb[go] + Osh[c * 68 + q];
        }
        __syncthreads();
    }
}

// ---------------- launcher ----------------
extern "C" void kernel_launch(void* const* d_in, const int* in_sizes, int n_in,
                              void* d_out, int out_size) {
    const float* x  = (const float*)d_in[0];
    const float* w1 = (const float*)d_in[1];
    const float* w2 = (const float*)d_in[2];
    const float* w3 = (const float*)d_in[3];
    const float* g1 = (const float*)d_in[4];
    const float* b1 = (const float*)d_in[5];
    const float* g2 = (const float*)d_in[6];
    const float* b2 = (const float*)d_in[7];
    const float* g3 = (const float*)d_in[8];
    const float* b3 = (const float*)d_in[9];
    float* out = (float*)d_out;

    cudaFuncSetAttribute(flash_mma, cudaFuncAttributeMaxDynamicSharedMemorySize, SM_TOT);

    zero_kernel<<<256, 256>>>();
    convx_kernel<<<1024, 256>>>(x);
    mean_kernel<<<256, 256>>>(x);
    gram_mma<<<dim3(4, 4, 16), 256>>>(0);
    fold_kernel<<<320, 256>>>(w1, w2, w3, g1, b1, g2, b2, g3, b3);
    qkd_kernel<<<dim3(5, 64, 4), 256>>>(x);
    flash_mma<<<dim3(64, 4), 256, SM_TOT>>>(x, out);
}

// round 8
// speedup vs baseline: 4.0810x; 1.1901x over previous
#include <cuda_runtime.h>
#include <cuda_bf16.h>
#include <cstdint>

#define BB 4
#define CN 256
#define NN 4096
#define OTOT 320
#define BN_TOT 16384.0f
#define KTOT 16384

// ---------------- device scratch ----------------
__device__ float g_mx[CN];                            // raw channel sums
__device__ float g_G[CN * CN];
__device__ float g_Bf[OTOT];
__device__ __nv_bfloat16 g_Wh[OTOT * CN];             // folded W hi, [o][c]
__device__ __nv_bfloat16 g_Wl[OTOT * CN];             // folded W lo, [o][c]
__device__ __nv_bfloat16 g_xh[(size_t)CN * KTOT];     // x hi, [c][b*n]
__device__ __nv_bfloat16 g_xl[(size_t)CN * KTOT];     // x lo, [c][b*n]
__device__ __nv_bfloat16 g_xTh[(size_t)KTOT * CN];    // x hi, [b*n][c]
__device__ __nv_bfloat16 g_xTl[(size_t)KTOT * CN];    // x lo, [b*n][c]
__device__ __nv_bfloat16 g_Qb[(size_t)BB * NN * 128]; // [b][n][qhi32|qlo32|qhi32|0]
__device__ __nv_bfloat16 g_Kb[(size_t)BB * NN * 128]; // [b][n][khi32|khi32|klo32|0]
__device__ __nv_bfloat16 g_Vb[(size_t)BB * CN * NN];  // bf16, [b][c][n]

// ---------------- mma.sync / async helpers ----------------
__device__ __forceinline__ void mma_bf16_16816(float* c, uint32_t a0, uint32_t a1,
                                               uint32_t a2, uint32_t a3,
                                               uint32_t b0, uint32_t b1) {
    asm volatile("mma.sync.aligned.m16n8k16.row.col.f32.bf16.bf16.f32 "
        "{%0,%1,%2,%3}, {%4,%5,%6,%7}, {%8,%9}, {%0,%1,%2,%3};"
        : "+f"(c[0]), "+f"(c[1]), "+f"(c[2]), "+f"(c[3])
        : "r"(a0), "r"(a1), "r"(a2), "r"(a3), "r"(b0), "r"(b1));
}
__device__ __forceinline__ void cp16(uint32_t dst, const void* src) {
    asm volatile("cp.async.cg.shared.global [%0], [%1], 16;" :: "r"(dst), "l"(src));
}
#define CP_COMMIT() asm volatile("cp.async.commit_group;" ::: "memory")
#define CP_WAIT0()  asm volatile("cp.async.wait_group 0;" ::: "memory")
#define CP_WAIT1()  asm volatile("cp.async.wait_group 1;" ::: "memory")
__device__ __forceinline__ uint32_t smem_u32(const void* p) {
    uint32_t a;
    asm("{ .reg .u64 t; cvta.to.shared.u64 t, %1; cvt.u32.u64 %0, t; }" : "=r"(a) : "l"(p));
    return a;
}
__device__ __forceinline__ uint32_t pack_bf2(float a, float b) {
    __nv_bfloat162 h = __floats2bfloat162_rn(a, b);
    return *(uint32_t*)&h;
}

// ---------------- prologue ----------------
__global__ void zero_kernel() {
    int i = blockIdx.x * blockDim.x + threadIdx.x;
    g_G[i] = 0.0f;
    if (i < CN) g_mx[i] = 0.0f;
}

// tiled transpose/convert: x -> bf16 hi/lo in [c][bn] AND [bn][c]; fused channel sums
__global__ void convx_kernel(const float* __restrict__ x) {
    __shared__ float tile[64][65];
    int n0 = blockIdx.x * 64, c0 = blockIdx.y * 64, b = blockIdx.z;
    int tid = threadIdx.x;
    int rr = tid >> 6, jj = tid & 63;
    const float* xb = x + ((size_t)b * CN + c0) * NN + n0;
    #pragma unroll
    for (int r = 0; r < 16; ++r) {
        int i = r * 4 + rr;
        tile[i][jj] = xb[(size_t)i * NN + jj];
    }
    __syncthreads();
    if (tid < 64) {
        float s = 0.0f;
        #pragma unroll
        for (int j = 0; j < 64; ++j) s += tile[tid][j];
        atomicAdd(&g_mx[c0 + tid], s);
    }
    size_t bn0 = (size_t)b * NN + n0;
    #pragma unroll
    for (int r = 0; r < 16; ++r) {
        int i = r * 4 + rr;
        float v = tile[i][jj];
        __nv_bfloat16 hi = __float2bfloat16(v);
        __nv_bfloat16 lo = __float2bfloat16(v - __bfloat162float(hi));
        size_t off = (size_t)(c0 + i) * KTOT + bn0 + jj;
        g_xh[off] = hi; g_xl[off] = lo;
    }
    #pragma unroll
    for (int r = 0; r < 16; ++r) {
        int i = r * 4 + rr;           // n index
        float v = tile[jj][i];        // [c=jj][n=i]
        __nv_bfloat16 hi = __float2bfloat16(v);
        __nv_bfloat16 lo = __float2bfloat16(v - __bfloat162float(hi));
        size_t off = (bn0 + i) * CN + c0 + jj;
        g_xTh[off] = hi; g_xTl[off] = lo;
    }
}

// ---------------- Gram via mma.sync (hi/lo bf16 compensation) ----------------
#define GR_STRIDE 144
#define GR_MAT (64 * GR_STRIDE)
__global__ void __launch_bounds__(256, 2)
gram_mma(int dummy) {
    __shared__ __align__(16) char smem[4 * GR_MAT];
    uint32_t sb = smem_u32(smem);
    int tid = threadIdx.x;
    int lane = tid & 31, wid = tid >> 5;
    int g = lane >> 2, t = lane & 3;
    int wm = wid >> 2, wn = wid & 3;
    int c0 = blockIdx.x * 64, c1 = blockIdx.y * 64;
    int kseg = blockIdx.z * 1024;

    float C[2][2][4] = {};

    for (int ch = 0; ch < 16; ++ch) {
        int k0 = kseg + ch * 64;
        __syncthreads();
        #pragma unroll
        for (int i = tid; i < 512; i += 256) {
            int row = i >> 3, col = i & 7;
            cp16(sb + 0 * GR_MAT + row * GR_STRIDE + col * 16,
                 g_xh + (size_t)(c0 + row) * KTOT + k0 + col * 8);
            cp16(sb + 1 * GR_MAT + row * GR_STRIDE + col * 16,
                 g_xl + (size_t)(c0 + row) * KTOT + k0 + col * 8);
            cp16(sb + 2 * GR_MAT + row * GR_STRIDE + col * 16,
                 g_xh + (size_t)(c1 + row) * KTOT + k0 + col * 8);
            cp16(sb + 3 * GR_MAT + row * GR_STRIDE + col * 16,
                 g_xl + (size_t)(c1 + row) * KTOT + k0 + col * 8);
        }
        CP_COMMIT();
        CP_WAIT0();
        __syncthreads();
        const char* Ah = smem;
        const char* Al = smem + GR_MAT;
        const char* Bh = smem + 2 * GR_MAT;
        const char* Bl = smem + 3 * GR_MAT;
        #pragma unroll
        for (int ks = 0; ks < 4; ++ks) {
            int koff = ks * 32 + t * 4;
            uint32_t ah[2][4], al[2][4];
            #pragma unroll
            for (int fm = 0; fm < 2; ++fm) {
                int r = wm * 32 + fm * 16 + g;
                ah[fm][0] = *(const uint32_t*)(Ah + r * GR_STRIDE + koff);
                ah[fm][1] = *(const uint32_t*)(Ah + (r + 8) * GR_STRIDE + koff);
                ah[fm][2] = *(const uint32_t*)(Ah + r * GR_STRIDE + koff + 16);
                ah[fm][3] = *(const uint32_t*)(Ah + (r + 8) * GR_STRIDE + koff + 16);
                al[fm][0] = *(const uint32_t*)(Al + r * GR_STRIDE + koff);
                al[fm][1] = *(const uint32_t*)(Al + (r + 8) * GR_STRIDE + koff);
                al[fm][2] = *(const uint32_t*)(Al + r * GR_STRIDE + koff + 16);
                al[fm][3] = *(const uint32_t*)(Al + (r + 8) * GR_STRIDE + koff + 16);
            }
            #pragma unroll
            for (int fn = 0; fn < 2; ++fn) {
                int r = wn * 16 + fn * 8 + g;
                uint32_t bh0 = *(const uint32_t*)(Bh + r * GR_STRIDE + koff);
                uint32_t bh1 = *(const uint32_t*)(Bh + r * GR_STRIDE + koff + 16);
                uint32_t bl0 = *(const uint32_t*)(Bl + r * GR_STRIDE + koff);
                uint32_t bl1 = *(const uint32_t*)(Bl + r * GR_STRIDE + koff + 16);
                #pragma unroll
                for (int fm = 0; fm < 2; ++fm) {
                    mma_bf16_16816(C[fm][fn], ah[fm][0], ah[fm][1], ah[fm][2], ah[fm][3], bh0, bh1);
                    mma_bf16_16816(C[fm][fn], ah[fm][0], ah[fm][1], ah[fm][2], ah[fm][3], bl0, bl1);
                    mma_bf16_16816(C[fm][fn], al[fm][0], al[fm][1], al[fm][2], al[fm][3], bh0, bh1);
                }
            }
        }
    }
    #pragma unroll
    for (int fm = 0; fm < 2; ++fm) {
        #pragma unroll
        for (int fn = 0; fn < 2; ++fn) {
            int r0 = c0 + wm * 32 + fm * 16 + g;
            int cc = c1 + wn * 16 + fn * 8 + 2 * t;
            atomicAdd(&g_G[r0 * CN + cc],           C[fm][fn][0]);
            atomicAdd(&g_G[r0 * CN + cc + 1],       C[fm][fn][1]);
            atomicAdd(&g_G[(r0 + 8) * CN + cc],     C[fm][fn][2]);
            atomicAdd(&g_G[(r0 + 8) * CN + cc + 1], C[fm][fn][3]);
        }
    }
}

// ---------------- fold BN, emit bf16 hi/lo weights ----------------
__global__ void fold_kernel(const float* __restrict__ w1, const float* __restrict__ w2,
                            const float* __restrict__ w3,
                            const float* __restrict__ g1, const float* __restrict__ b1,
                            const float* __restrict__ g2, const float* __restrict__ b2,
                            const float* __restrict__ g3, const float* __restrict__ b3) {
    int o = blockIdx.x, tid = threadIdx.x;
    const float* w; float gg, bb;
    if (o < 32)      { w = w1 + o * CN;        gg = g1[o];      bb = b1[o]; }
    else if (o < 64) { w = w2 + (o - 32) * CN; gg = g2[o - 32]; bb = b2[o - 32]; }
    else             { w = w3 + (o - 64) * CN; gg = g3[o - 64]; bb = b3[o - 64]; }
    __shared__ float ws[256], redE[256], redM[256], sc_sh;
    ws[tid] = w[tid]; __syncthreads();
    float a0 = 0.0f, a1 = 0.0f, a2 = 0.0f, a3 = 0.0f;
    #pragma unroll 8
    for (int c = 0; c < CN; c += 4) {
        a0 += g_G[(c + 0) * CN + tid] * ws[c + 0];
        a1 += g_G[(c + 1) * CN + tid] * ws[c + 1];
        a2 += g_G[(c + 2) * CN + tid] * ws[c + 2];
        a3 += g_G[(c + 3) * CN + tid] * ws[c + 3];
    }
    redE[tid] = (a0 + a1 + a2 + a3) * ws[tid];
    redM[tid] = ws[tid] * g_mx[tid] * (1.0f / BN_TOT);
    __syncthreads();
    for (int st = 128; st > 0; st >>= 1) {
        if (tid < st) { redE[tid] += redE[tid + st]; redM[tid] += redM[tid + st]; }
        __syncthreads();
    }
    if (tid == 0) {
        float m = redM[0], E = redE[0] * (1.0f / BN_TOT);
        float rs = rsqrtf(E - m * m + 1e-5f);
        float sc = gg * rs;
        sc_sh = sc;
        g_Bf[o] = bb - sc * m;
    }
    __syncthreads();
    float wf = sc_sh * ws[tid];
    __nv_bfloat16 hi = __float2bfloat16(wf);
    __nv_bfloat16 lo = __float2bfloat16(wf - __bfloat162float(hi));
    g_Wh[o * CN + tid] = hi;
    g_Wl[o * CN + tid] = lo;
}

// ---------------- qkd via mma.sync: Z[o][bn] = relu(W x + b) -> Qb/Kb/Vb ----------------
// Block 64 o x 256 bn, 8 warps = 2(o) x 4(n), warp 32x64. k-chunks of 64.
// SMEM: Wh@0 (64x144), Wl@9216, Xh@18432 (256x144), Xl@55296 -> 92160 B dynamic.
#define QK_SM 92160
__global__ void __launch_bounds__(256, 2)
qkd_mma(int dummy) {
    extern __shared__ __align__(16) char smem[];
    uint32_t sb = smem_u32(smem);
    int tid = threadIdx.x;
    int lane = tid & 31, wid = tid >> 5;
    int g = lane >> 2, t = lane & 3;
    int wm = wid >> 2, wn = wid & 3;
    int o0 = blockIdx.x * 64;
    int bn0 = blockIdx.y * 256;

    float C[2][8][4] = {};

    for (int kc = 0; kc < 4; ++kc) {
        int k0 = kc * 64;
        __syncthreads();
        // W tiles: 64 rows x 8 cp16 (128 B of k-data per row)
        #pragma unroll
        for (int i = tid; i < 512; i += 256) {
            int row = i >> 3, col = i & 7;
            cp16(sb + row * 144 + col * 16,        g_Wh + (size_t)(o0 + row) * CN + k0 + col * 8);
            cp16(sb + 9216 + row * 144 + col * 16, g_Wl + (size_t)(o0 + row) * CN + k0 + col * 8);
        }
        // X tiles: 256 rows x 8 cp16
        #pragma unroll
        for (int i = tid; i < 2048; i += 256) {
            int row = i >> 3, col = i & 7;
            cp16(sb + 18432 + row * 144 + col * 16, g_xTh + (bn0 + row) * (size_t)CN + k0 + col * 8);
            cp16(sb + 55296 + row * 144 + col * 16, g_xTl + (bn0 + row) * (size_t)CN + k0 + col * 8);
        }
        CP_COMMIT();
        CP_WAIT0();
        __syncthreads();
        const char* Wh = smem;
        const char* Wl = smem + 9216;
        const char* Xh = smem + 18432;
        const char* Xl = smem + 55296;
        #pragma unroll
        for (int ks = 0; ks < 4; ++ks) {
            int koff = ks * 32 + t * 4;
            uint32_t ah[2][4], al[2][4];
            #pragma unroll
            for (int fm = 0; fm < 2; ++fm) {
                int r = wm * 32 + fm * 16 + g;
                ah[fm][0] = *(const uint32_t*)(Wh + r * 144 + koff);
                ah[fm][1] = *(const uint32_t*)(Wh + (r + 8) * 144 + koff);
                ah[fm][2] = *(const uint32_t*)(Wh + r * 144 + koff + 16);
                ah[fm][3] = *(const uint32_t*)(Wh + (r + 8) * 144 + koff + 16);
                al[fm][0] = *(const uint32_t*)(Wl + r * 144 + koff);
                al[fm][1] = *(const uint32_t*)(Wl + (r + 8) * 144 + koff);
                al[fm][2] = *(const uint32_t*)(Wl + r * 144 + koff + 16);
                al[fm][3] = *(const uint32_t*)(Wl + (r + 8) * 144 + koff + 16);
            }
            #pragma unroll
            for (int fn = 0; fn < 8; ++fn) {
                int r = wn * 64 + fn * 8 + g;
                uint32_t bh0 = *(const uint32_t*)(Xh + r * 144 + koff);
                uint32_t bh1 = *(const uint32_t*)(Xh + r * 144 + koff + 16);
                uint32_t bl0 = *(const uint32_t*)(Xl + r * 144 + koff);
                uint32_t bl1 = *(const uint32_t*)(Xl + r * 144 + koff + 16);
                #pragma unroll
                for (int fm = 0; fm < 2; ++fm) {
                    mma_bf16_16816(C[fm][fn], ah[fm][0], ah[fm][1], ah[fm][2], ah[fm][3], bh0, bh1);
                    mma_bf16_16816(C[fm][fn], ah[fm][0], ah[fm][1], ah[fm][2], ah[fm][3], bl0, bl1);
                    mma_bf16_16816(C[fm][fn], al[fm][0], al[fm][1], al[fm][2], al[fm][3], bh0, bh1);
                }
            }
        }
    }

    // epilogue: relu + route to Qb/Kb/Vb
    __nv_bfloat16 zero = __float2bfloat16(0.0f);
    #pragma unroll
    for (int fm = 0; fm < 2; ++fm) {
        int obase = o0 + wm * 32 + fm * 16 + g;
        float bias0 = g_Bf[obase], bias1 = g_Bf[obase + 8];
        #pragma unroll
        for (int fn = 0; fn < 8; ++fn) {
            int bncol = bn0 + wn * 64 + fn * 8 + 2 * t;
            int b = bncol >> 12, n = bncol & 4095;
            #pragma unroll
            for (int rr = 0; rr < 2; ++rr) {
                int o = obase + rr * 8;
                float v0 = fmaxf(C[fm][fn][rr * 2 + 0] + (rr ? bias1 : bias0), 0.0f);
                float v1 = fmaxf(C[fm][fn][rr * 2 + 1] + (rr ? bias1 : bias0), 0.0f);
                if (o >= 64) {
                    *(uint32_t*)(g_Vb + ((size_t)b * CN + (o - 64)) * NN + n) = pack_bf2(v0, v1);
                } else {
                    #pragma unroll
                    for (int e = 0; e < 2; ++e) {
                        float v = e ? v1 : v0;
                        __nv_bfloat16 hi = __float2bfloat16(v);
                        __nv_bfloat16 lo = __float2bfloat16(v - __bfloat162float(hi));
                        size_t base = ((size_t)b * NN + n + e) * 128;
                        if (o < 32) {
                            g_Qb[base + o] = hi; g_Qb[base + 32 + o] = lo;
                            g_Qb[base + 64 + o] = hi; g_Qb[base + 96 + o] = zero;
                        } else {
                            int oc = o - 32;
                            g_Kb[base + oc] = hi; g_Kb[base + 32 + oc] = hi;
                            g_Kb[base + 64 + oc] = lo; g_Kb[base + 96 + oc] = zero;
                        }
                    }
                }
            }
        }
    }
}

// ---------------- flash attention via mma.sync, cp.async double-buffered ----------------
#define KS_OFF 0
#define KS_BUF 8704
#define VS_OFF 17408
#define VS_BUF 20480
#define PS_OFF 58368
#define STM_OFF 63488
#define STL_OFF 64000
#define SM_TOT 64512
#define OSH_OFF VS_OFF

__global__ void __launch_bounds__(256, 2)
flash_mma(const float* __restrict__ x, float* __restrict__ out) {
    extern __shared__ __align__(16) char smem[];
    uint32_t sb = smem_u32(smem);
    int tid = threadIdx.x;
    int lane = tid & 31, wid = tid >> 5;
    int g = lane >> 2, t = lane & 3;
    int mrow = wid & 3, khalf = wid >> 2;
    int q0 = mrow * 16;
    int b = blockIdx.y, m0 = blockIdx.x * 64;

    float* stM = (float*)(smem + STM_OFF);
    float* stL = (float*)(smem + STL_OFF);

    uint32_t qa[6][4];
    {
        const __nv_bfloat16* qr0 = g_Qb + ((size_t)b * NN + m0 + q0 + g) * 128;
        const __nv_bfloat16* qr1 = qr0 + (size_t)8 * 128;
        #pragma unroll
        for (int ks = 0; ks < 6; ++ks) {
            int e = ks * 16 + 2 * t;
            qa[ks][0] = *(const uint32_t*)(qr0 + e);
            qa[ks][1] = *(const uint32_t*)(qr1 + e);
            qa[ks][2] = *(const uint32_t*)(qr0 + e + 8);
            qa[ks][3] = *(const uint32_t*)(qr1 + e + 8);
        }
    }

    const char* kgb = (const char*)(g_Kb + ((size_t)b * NN) * 128);
    const char* vgb = (const char*)(g_Vb + (size_t)b * CN * NN);

    {
        #pragma unroll
        for (int i = tid; i < 512; i += 256) {
            int row = i >> 4, col = i & 15;
            cp16(sb + KS_OFF + row * 272 + col * 16, kgb + (size_t)row * 256 + col * 16);
        }
        #pragma unroll
        for (int i = tid; i < 1024; i += 256) {
            int c = i >> 2, j = i & 3;
            cp16(sb + VS_OFF + c * 80 + j * 16, vgb + (size_t)c * (NN * 2) + j * 16);
        }
        CP_COMMIT();
    }

    float D[16][4];
    #pragma unroll
    for (int nt = 0; nt < 16; ++nt) { D[nt][0] = D[nt][1] = D[nt][2] = D[nt][3] = 0.0f; }
    float m_run0 = -1e30f, m_run1 = -1e30f, l_run0 = 0.0f, l_run1 = 0.0f;

    for (int ch = 0; ch < 128; ++ch) {
        int buf = ch & 1;
        __syncthreads();
        if (ch + 1 < 128) {
            int n1 = (ch + 1) * 32;
            uint32_t kd = sb + KS_OFF + (buf ^ 1) * KS_BUF;
            uint32_t vd = sb + VS_OFF + (buf ^ 1) * VS_BUF;
            #pragma unroll
            for (int i = tid; i < 512; i += 256) {
                int row = i >> 4, col = i & 15;
                cp16(kd + row * 272 + col * 16, kgb + (size_t)(n1 + row) * 256 + col * 16);
            }
            #pragma unroll
            for (int i = tid; i < 1024; i += 256) {
                int c = i >> 2, j = i & 3;
                cp16(vd + c * 80 + j * 16, vgb + (size_t)c * (NN * 2) + (size_t)n1 * 2 + j * 16);
            }
        }
        CP_COMMIT();
        CP_WAIT1();
        __syncthreads();

        const char* ksm = smem + KS_OFF + buf * KS_BUF;
        float sc[2][4] = {};
        #pragma unroll
        for (int ks = 0; ks < 6; ++ks) {
            #pragma unroll
            for (int nt = 0; nt < 2; ++nt) {
                const char* kbase = ksm + (khalf * 16 + nt * 8 + g) * 272 + ks * 32 + t * 4;
                uint32_t b0 = *(const uint32_t*)(kbase);
                uint32_t b1 = *(const uint32_t*)(kbase + 16);
                mma_bf16_16816(sc[nt], qa[ks][0], qa[ks][1], qa[ks][2], qa[ks][3], b0, b1);
            }
        }
        float mp0 = fmaxf(fmaxf(sc[0][0], sc[0][1]), fmaxf(sc[1][0], sc[1][1]));
        float mp1 = fmaxf(fmaxf(sc[0][2], sc[0][3]), fmaxf(sc[1][2], sc[1][3]));
        mp0 = fmaxf(mp0, __shfl_xor_sync(0xffffffffu, mp0, 1));
        mp0 = fmaxf(mp0, __shfl_xor_sync(0xffffffffu, mp0, 2));
        mp1 = fmaxf(mp1, __shfl_xor_sync(0xffffffffu, mp1, 1));
        mp1 = fmaxf(mp1, __shfl_xor_sync(0xffffffffu, mp1, 2));
        if (t == 0) {
            stM[khalf * 64 + q0 + g] = mp0;
            stM[khalf * 64 + q0 + 8 + g] = mp1;
        }
        __syncthreads();
        float mt0 = fmaxf(stM[q0 + g], stM[64 + q0 + g]);
        float mt1 = fmaxf(stM[q0 + 8 + g], stM[64 + q0 + 8 + g]);
        float mn0 = fmaxf(m_run0, mt0), mn1 = fmaxf(m_run1, mt1);
        float f0 = __expf(m_run0 - mn0), f1 = __expf(m_run1 - mn1);
        m_run0 = mn0; m_run1 = mn1;

        float e00 = __expf(sc[0][0] - mn0), e01 = __expf(sc[0][1] - mn0);
        float e02 = __expf(sc[0][2] - mn1), e03 = __expf(sc[0][3] - mn1);
        float e10 = __expf(sc[1][0] - mn0), e11 = __expf(sc[1][1] - mn0);
        float e12 = __expf(sc[1][2] - mn1), e13 = __expf(sc[1][3] - mn1);
        float ls0 = e00 + e01 + e10 + e11;
        float ls1 = e02 + e03 + e12 + e13;

        uint32_t paA[2][4];
        paA[khalf][0] = pack_bf2(e00, e01);
        paA[khalf][1] = pack_bf2(e02, e03);
        paA[khalf][2] = pack_bf2(e10, e11);
        paA[khalf][3] = pack_bf2(e12, e13);
        {
            char* pr0 = smem + PS_OFF + (q0 + g) * 80 + (khalf * 16 + 2 * t) * 2;
            char* pr1 = smem + PS_OFF + (q0 + 8 + g) * 80 + (khalf * 16 + 2 * t) * 2;
            *(uint32_t*)(pr0)      = paA[khalf][0];
            *(uint32_t*)(pr0 + 16) = paA[khalf][2];
            *(uint32_t*)(pr1)      = paA[khalf][1];
            *(uint32_t*)(pr1 + 16) = paA[khalf][3];
        }
        ls0 += __shfl_xor_sync(0xffffffffu, ls0, 1);
        ls0 += __shfl_xor_sync(0xffffffffu, ls0, 2);
        ls1 += __shfl_xor_sync(0xffffffffu, ls1, 1);
        ls1 += __shfl_xor_sync(0xffffffffu, ls1, 2);
        if (t == 0) {
            stL[khalf * 64 + q0 + g] = ls0;
            stL[khalf * 64 + q0 + 8 + g] = ls1;
        }
        uint32_t need = __ballot_sync(0xffffffffu, (f0 < 1.0f) || (f1 < 1.0f));
        if (need) {
            #pragma unroll
            for (int nt = 0; nt < 16; ++nt) {
                D[nt][0] *= f0; D[nt][1] *= f0;
                D[nt][2] *= f1; D[nt][3] *= f1;
            }
        }
        __syncthreads();
        l_run0 = l_run0 * f0 + stL[q0 + g] + stL[64 + q0 + g];
        l_run1 = l_run1 * f1 + stL[q0 + 8 + g] + stL[64 + q0 + 8 + g];

        {
            int oh = khalf ^ 1;
            const char* pb0 = smem + PS_OFF + (q0 + g) * 80 + (oh * 16 + 2 * t) * 2;
            const char* pb1 = smem + PS_OFF + (q0 + 8 + g) * 80 + (oh * 16 + 2 * t) * 2;
            paA[oh][0] = *(const uint32_t*)(pb0);
            paA[oh][1] = *(const uint32_t*)(pb1);
            paA[oh][2] = *(const uint32_t*)(pb0 + 16);
            paA[oh][3] = *(const uint32_t*)(pb1 + 16);
        }

        const char* vsm = smem + VS_OFF + buf * VS_BUF;
        #pragma unroll
        for (int nt = 0; nt < 16; ++nt) {
            const char* vb = vsm + (khalf * 128 + nt * 8 + g) * 80 + t * 4;
            #pragma unroll
            for (int ks2 = 0; ks2 < 2; ++ks2) {
                uint32_t b0 = *(const uint32_t*)(vb + ks2 * 32);
                uint32_t b1 = *(const uint32_t*)(vb + ks2 * 32 + 16);
                mma_bf16_16816(D[nt], paA[ks2][0], paA[ks2][1], paA[ks2][2], paA[ks2][3], b0, b1);
            }
        }
    }
    __syncthreads();

    float il0 = 1.0f / l_run0, il1 = 1.0f / l_run1;
    const float* xb = x + (size_t)b * CN * NN + m0;
    float* ob = out + (size_t)b * CN * NN + m0;
    float* Osh = (float*)(smem + OSH_OFF);
    #pragma unroll
    for (int h = 0; h < 2; ++h) {
        if (khalf == h) {
            #pragma unroll
            for (int nt = 0; nt < 16; ++nt) {
                int c = nt * 8 + 2 * t;
                Osh[c * 68 + q0 + g]           = D[nt][0] * il0;
                Osh[(c + 1) * 68 + q0 + g]     = D[nt][1] * il0;
                Osh[c * 68 + q0 + 8 + g]       = D[nt][2] * il1;
                Osh[(c + 1) * 68 + q0 + 8 + g] = D[nt][3] * il1;
            }
        }
        __syncthreads();
        #pragma unroll
        for (int i = tid; i < 8192; i += 256) {
            int c = i >> 6, q = i & 63;
            size_t go = (size_t)(h * 128 + c) * NN + q;
            ob[go] = xb[go] + Osh[c * 68 + q];
        }
        __syncthreads();
    }
}

// ---------------- launcher ----------------
extern "C" void kernel_launch(void* const* d_in, const int* in_sizes, int n_in,
                              void* d_out, int out_size) {
    const float* x  = (const float*)d_in[0];
    const float* w1 = (const float*)d_in[1];
    const float* w2 = (const float*)d_in[2];
    const float* w3 = (const float*)d_in[3];
    const float* g1 = (const float*)d_in[4];
    const float* b1 = (const float*)d_in[5];
    const float* g2 = (const float*)d_in[6];
    const float* b2 = (const float*)d_in[7];
    const float* g3 = (const float*)d_in[8];
    const float* b3 = (const float*)d_in[9];
    float* out = (float*)d_out;

    cudaFuncSetAttribute(flash_mma, cudaFuncAttributeMaxDynamicSharedMemorySize, SM_TOT);
    cudaFuncSetAttribute(qkd_mma, cudaFuncAttributeMaxDynamicSharedMemorySize, QK_SM);

    zero_kernel<<<256, 256>>>();
    convx_kernel<<<dim3(64, 4, 4), 256>>>(x);
    gram_mma<<<dim3(4, 4, 16), 256>>>(0);
    fold_kernel<<<320, 256>>>(w1, w2, w3, g1, b1, g2, b2, g3, b3);
    qkd_mma<<<dim3(5, 64), 256, QK_SM>>>(0);
    flash_mma<<<dim3(64, 4), 256, SM_TOT>>>(x, out);
}

// round 9
// speedup vs baseline: 4.4040x; 1.0791x over previous
#include <cuda_runtime.h>
#include <cuda_bf16.h>
#include <cstdint>

#define BB 4
#define CN 256
#define NN 4096
#define OTOT 320
#define BN_TOT 16384.0f
#define KTOT 16384

// ---------------- device scratch ----------------
__device__ float g_mx[CN];                            // raw channel sums
__device__ float g_G[CN * CN];
__device__ float g_Bf[OTOT];
__device__ __nv_bfloat16 g_Wh[OTOT * CN];             // folded W hi, [o][c]
__device__ __nv_bfloat16 g_Wl[OTOT * CN];             // folded W lo, [o][c]
__device__ __nv_bfloat16 g_xh[(size_t)CN * KTOT];     // x hi, [c][b*n]
__device__ __nv_bfloat16 g_xl[(size_t)CN * KTOT];     // x lo, [c][b*n]
__device__ __nv_bfloat16 g_xTh[(size_t)KTOT * CN];    // x hi, [b*n][c]
__device__ __nv_bfloat16 g_xTl[(size_t)KTOT * CN];    // x lo, [b*n][c]
__device__ __nv_bfloat16 g_Qb[(size_t)BB * NN * 128]; // [b][n][qhi32|qlo32|qhi32|0]
__device__ __nv_bfloat16 g_Kb[(size_t)BB * NN * 128]; // [b][n][khi32|khi32|klo32|0]
__device__ __nv_bfloat16 g_Vb[(size_t)BB * CN * NN];  // bf16, [b][c][n]

// ---------------- mma.sync / async helpers ----------------
__device__ __forceinline__ void mma_bf16_16816(float* c, uint32_t a0, uint32_t a1,
                                               uint32_t a2, uint32_t a3,
                                               uint32_t b0, uint32_t b1) {
    asm volatile("mma.sync.aligned.m16n8k16.row.col.f32.bf16.bf16.f32 "
        "{%0,%1,%2,%3}, {%4,%5,%6,%7}, {%8,%9}, {%0,%1,%2,%3};"
        : "+f"(c[0]), "+f"(c[1]), "+f"(c[2]), "+f"(c[3])
        : "r"(a0), "r"(a1), "r"(a2), "r"(a3), "r"(b0), "r"(b1));
}
__device__ __forceinline__ void cp16(uint32_t dst, const void* src) {
    asm volatile("cp.async.cg.shared.global [%0], [%1], 16;" :: "r"(dst), "l"(src));
}
#define CP_COMMIT() asm volatile("cp.async.commit_group;" ::: "memory")
#define CP_WAIT0()  asm volatile("cp.async.wait_group 0;" ::: "memory")
#define CP_WAIT1()  asm volatile("cp.async.wait_group 1;" ::: "memory")
__device__ __forceinline__ uint32_t smem_u32(const void* p) {
    uint32_t a;
    asm("{ .reg .u64 t; cvta.to.shared.u64 t, %1; cvt.u32.u64 %0, t; }" : "=r"(a) : "l"(p));
    return a;
}
__device__ __forceinline__ uint32_t pack_bf2(float a, float b) {
    __nv_bfloat162 h = __floats2bfloat162_rn(a, b);
    return *(uint32_t*)&h;
}

// ---------------- prologue ----------------
__global__ void zero_kernel() {
    int i = blockIdx.x * blockDim.x + threadIdx.x;
    g_G[i] = 0.0f;
    if (i < CN) g_mx[i] = 0.0f;
}

// tiled transpose/convert: x -> bf16 hi/lo in [c][bn] AND [bn][c]; fused channel sums
__global__ void convx_kernel(const float* __restrict__ x) {
    __shared__ float tile[64][65];
    int n0 = blockIdx.x * 64, c0 = blockIdx.y * 64, b = blockIdx.z;
    int tid = threadIdx.x;
    int rr = tid >> 6, jj = tid & 63;
    const float* xb = x + ((size_t)b * CN + c0) * NN + n0;
    #pragma unroll
    for (int r = 0; r < 16; ++r) {
        int i = r * 4 + rr;
        tile[i][jj] = xb[(size_t)i * NN + jj];
    }
    __syncthreads();
    if (tid < 64) {
        float s = 0.0f;
        #pragma unroll
        for (int j = 0; j < 64; ++j) s += tile[tid][j];
        atomicAdd(&g_mx[c0 + tid], s);
    }
    size_t bn0 = (size_t)b * NN + n0;
    #pragma unroll
    for (int r = 0; r < 16; ++r) {
        int i = r * 4 + rr;
        float v = tile[i][jj];
        __nv_bfloat16 hi = __float2bfloat16(v);
        __nv_bfloat16 lo = __float2bfloat16(v - __bfloat162float(hi));
        size_t off = (size_t)(c0 + i) * KTOT + bn0 + jj;
        g_xh[off] = hi; g_xl[off] = lo;
    }
    #pragma unroll
    for (int r = 0; r < 16; ++r) {
        int i = r * 4 + rr;           // n index
        float v = tile[jj][i];        // [c=jj][n=i]
        __nv_bfloat16 hi = __float2bfloat16(v);
        __nv_bfloat16 lo = __float2bfloat16(v - __bfloat162float(hi));
        size_t off = (bn0 + i) * CN + c0 + jj;
        g_xTh[off] = hi; g_xTl[off] = lo;
    }
}

// ---------------- Gram via mma.sync (hi/lo bf16 compensation) ----------------
#define GR_STRIDE 144
#define GR_MAT (64 * GR_STRIDE)
__global__ void __launch_bounds__(256, 2)
gram_mma(int dummy) {
    __shared__ __align__(16) char smem[4 * GR_MAT];
    uint32_t sb = smem_u32(smem);
    int tid = threadIdx.x;
    int lane = tid & 31, wid = tid >> 5;
    int g = lane >> 2, t = lane & 3;
    int wm = wid >> 2, wn = wid & 3;
    int c0 = blockIdx.x * 64, c1 = blockIdx.y * 64;
    int kseg = blockIdx.z * 1024;

    float C[2][2][4] = {};

    for (int ch = 0; ch < 16; ++ch) {
        int k0 = kseg + ch * 64;
        __syncthreads();
        #pragma unroll
        for (int i = tid; i < 512; i += 256) {
            int row = i >> 3, col = i & 7;
            cp16(sb + 0 * GR_MAT + row * GR_STRIDE + col * 16,
                 g_xh + (size_t)(c0 + row) * KTOT + k0 + col * 8);
            cp16(sb + 1 * GR_MAT + row * GR_STRIDE + col * 16,
                 g_xl + (size_t)(c0 + row) * KTOT + k0 + col * 8);
            cp16(sb + 2 * GR_MAT + row * GR_STRIDE + col * 16,
                 g_xh + (size_t)(c1 + row) * KTOT + k0 + col * 8);
            cp16(sb + 3 * GR_MAT + row * GR_STRIDE + col * 16,
                 g_xl + (size_t)(c1 + row) * KTOT + k0 + col * 8);
        }
        CP_COMMIT();
        CP_WAIT0();
        __syncthreads();
        const char* Ah = smem;
        const char* Al = smem + GR_MAT;
        const char* Bh = smem + 2 * GR_MAT;
        const char* Bl = smem + 3 * GR_MAT;
        #pragma unroll
        for (int ks = 0; ks < 4; ++ks) {
            int koff = ks * 32 + t * 4;
            uint32_t ah[2][4], al[2][4];
            #pragma unroll
            for (int fm = 0; fm < 2; ++fm) {
                int r = wm * 32 + fm * 16 + g;
                ah[fm][0] = *(const uint32_t*)(Ah + r * GR_STRIDE + koff);
                ah[fm][1] = *(const uint32_t*)(Ah + (r + 8) * GR_STRIDE + koff);
                ah[fm][2] = *(const uint32_t*)(Ah + r * GR_STRIDE + koff + 16);
                ah[fm][3] = *(const uint32_t*)(Ah + (r + 8) * GR_STRIDE + koff + 16);
                al[fm][0] = *(const uint32_t*)(Al + r * GR_STRIDE + koff);
                al[fm][1] = *(const uint32_t*)(Al + (r + 8) * GR_STRIDE + koff);
                al[fm][2] = *(const uint32_t*)(Al + r * GR_STRIDE + koff + 16);
                al[fm][3] = *(const uint32_t*)(Al + (r + 8) * GR_STRIDE + koff + 16);
            }
            #pragma unroll
            for (int fn = 0; fn < 2; ++fn) {
                int r = wn * 16 + fn * 8 + g;
                uint32_t bh0 = *(const uint32_t*)(Bh + r * GR_STRIDE + koff);
                uint32_t bh1 = *(const uint32_t*)(Bh + r * GR_STRIDE + koff + 16);
                uint32_t bl0 = *(const uint32_t*)(Bl + r * GR_STRIDE + koff);
                uint32_t bl1 = *(const uint32_t*)(Bl + r * GR_STRIDE + koff + 16);
                #pragma unroll
                for (int fm = 0; fm < 2; ++fm) {
                    mma_bf16_16816(C[fm][fn], ah[fm][0], ah[fm][1], ah[fm][2], ah[fm][3], bh0, bh1);
                    mma_bf16_16816(C[fm][fn], ah[fm][0], ah[fm][1], ah[fm][2], ah[fm][3], bl0, bl1);
                    mma_bf16_16816(C[fm][fn], al[fm][0], al[fm][1], al[fm][2], al[fm][3], bh0, bh1);
                }
            }
        }
    }
    #pragma unroll
    for (int fm = 0; fm < 2; ++fm) {
        #pragma unroll
        for (int fn = 0; fn < 2; ++fn) {
            int r0 = c0 + wm * 32 + fm * 16 + g;
            int cc = c1 + wn * 16 + fn * 8 + 2 * t;
            atomicAdd(&g_G[r0 * CN + cc],           C[fm][fn][0]);
            atomicAdd(&g_G[r0 * CN + cc + 1],       C[fm][fn][1]);
            atomicAdd(&g_G[(r0 + 8) * CN + cc],     C[fm][fn][2]);
            atomicAdd(&g_G[(r0 + 8) * CN + cc + 1], C[fm][fn][3]);
        }
    }
}

// ---------------- fold BN, emit bf16 hi/lo weights ----------------
__global__ void fold_kernel(const float* __restrict__ w1, const float* __restrict__ w2,
                            const float* __restrict__ w3,
                            const float* __restrict__ g1, const float* __restrict__ b1,
                            const float* __restrict__ g2, const float* __restrict__ b2,
                            const float* __restrict__ g3, const float* __restrict__ b3) {
    int o = blockIdx.x, tid = threadIdx.x;
    const float* w; float gg, bb;
    if (o < 32)      { w = w1 + o * CN;        gg = g1[o];      bb = b1[o]; }
    else if (o < 64) { w = w2 + (o - 32) * CN; gg = g2[o - 32]; bb = b2[o - 32]; }
    else             { w = w3 + (o - 64) * CN; gg = g3[o - 64]; bb = b3[o - 64]; }
    __shared__ float ws[256], redE[256], redM[256], sc_sh;
    ws[tid] = w[tid]; __syncthreads();
    float a0 = 0.0f, a1 = 0.0f, a2 = 0.0f, a3 = 0.0f;
    #pragma unroll 8
    for (int c = 0; c < CN; c += 4) {
        a0 += g_G[(c + 0) * CN + tid] * ws[c + 0];
        a1 += g_G[(c + 1) * CN + tid] * ws[c + 1];
        a2 += g_G[(c + 2) * CN + tid] * ws[c + 2];
        a3 += g_G[(c + 3) * CN + tid] * ws[c + 3];
    }
    redE[tid] = (a0 + a1 + a2 + a3) * ws[tid];
    redM[tid] = ws[tid] * g_mx[tid] * (1.0f / BN_TOT);
    __syncthreads();
    for (int st = 128; st > 0; st >>= 1) {
        if (tid < st) { redE[tid] += redE[tid + st]; redM[tid] += redM[tid + st]; }
        __syncthreads();
    }
    if (tid == 0) {
        float m = redM[0], E = redE[0] * (1.0f / BN_TOT);
        float rs = rsqrtf(E - m * m + 1e-5f);
        float sc = gg * rs;
        sc_sh = sc;
        g_Bf[o] = bb - sc * m;
    }
    __syncthreads();
    float wf = sc_sh * ws[tid];
    __nv_bfloat16 hi = __float2bfloat16(wf);
    __nv_bfloat16 lo = __float2bfloat16(wf - __bfloat162float(hi));
    g_Wh[o * CN + tid] = hi;
    g_Wl[o * CN + tid] = lo;
}

// ---------------- qkd via mma.sync: Z[o][bn] = relu(W x + b) -> Qb/Kb/Vb ----------------
#define QK_SM 92160
__global__ void __launch_bounds__(256, 2)
qkd_mma(int dummy) {
    extern __shared__ __align__(16) char smem[];
    uint32_t sb = smem_u32(smem);
    int tid = threadIdx.x;
    int lane = tid & 31, wid = tid >> 5;
    int g = lane >> 2, t = lane & 3;
    int wm = wid >> 2, wn = wid & 3;
    int o0 = blockIdx.x * 64;
    int bn0 = blockIdx.y * 256;

    float C[2][8][4] = {};

    for (int kc = 0; kc < 4; ++kc) {
        int k0 = kc * 64;
        __syncthreads();
        #pragma unroll
        for (int i = tid; i < 512; i += 256) {
            int row = i >> 3, col = i & 7;
            cp16(sb + row * 144 + col * 16,        g_Wh + (size_t)(o0 + row) * CN + k0 + col * 8);
            cp16(sb + 9216 + row * 144 + col * 16, g_Wl + (size_t)(o0 + row) * CN + k0 + col * 8);
        }
        #pragma unroll
        for (int i = tid; i < 2048; i += 256) {
            int row = i >> 3, col = i & 7;
            cp16(sb + 18432 + row * 144 + col * 16, g_xTh + (bn0 + row) * (size_t)CN + k0 + col * 8);
            cp16(sb + 55296 + row * 144 + col * 16, g_xTl + (bn0 + row) * (size_t)CN + k0 + col * 8);
        }
        CP_COMMIT();
        CP_WAIT0();
        __syncthreads();
        const char* Wh = smem;
        const char* Wl = smem + 9216;
        const char* Xh = smem + 18432;
        const char* Xl = smem + 55296;
        #pragma unroll
        for (int ks = 0; ks < 4; ++ks) {
            int koff = ks * 32 + t * 4;
            uint32_t ah[2][4], al[2][4];
            #pragma unroll
            for (int fm = 0; fm < 2; ++fm) {
                int r = wm * 32 + fm * 16 + g;
                ah[fm][0] = *(const uint32_t*)(Wh + r * 144 + koff);
                ah[fm][1] = *(const uint32_t*)(Wh + (r + 8) * 144 + koff);
                ah[fm][2] = *(const uint32_t*)(Wh + r * 144 + koff + 16);
                ah[fm][3] = *(const uint32_t*)(Wh + (r + 8) * 144 + koff + 16);
                al[fm][0] = *(const uint32_t*)(Wl + r * 144 + koff);
                al[fm][1] = *(const uint32_t*)(Wl + (r + 8) * 144 + koff);
                al[fm][2] = *(const uint32_t*)(Wl + r * 144 + koff + 16);
                al[fm][3] = *(const uint32_t*)(Wl + (r + 8) * 144 + koff + 16);
            }
            #pragma unroll
            for (int fn = 0; fn < 8; ++fn) {
                int r = wn * 64 + fn * 8 + g;
                uint32_t bh0 = *(const uint32_t*)(Xh + r * 144 + koff);
                uint32_t bh1 = *(const uint32_t*)(Xh + r * 144 + koff + 16);
                uint32_t bl0 = *(const uint32_t*)(Xl + r * 144 + koff);
                uint32_t bl1 = *(const uint32_t*)(Xl + r * 144 + koff + 16);
                #pragma unroll
                for (int fm = 0; fm < 2; ++fm) {
                    mma_bf16_16816(C[fm][fn], ah[fm][0], ah[fm][1], ah[fm][2], ah[fm][3], bh0, bh1);
                    mma_bf16_16816(C[fm][fn], ah[fm][0], ah[fm][1], ah[fm][2], ah[fm][3], bl0, bl1);
                    mma_bf16_16816(C[fm][fn], al[fm][0], al[fm][1], al[fm][2], al[fm][3], bh0, bh1);
                }
            }
        }
    }

    __nv_bfloat16 zero = __float2bfloat16(0.0f);
    #pragma unroll
    for (int fm = 0; fm < 2; ++fm) {
        int obase = o0 + wm * 32 + fm * 16 + g;
        float bias0 = g_Bf[obase], bias1 = g_Bf[obase + 8];
        #pragma unroll
        for (int fn = 0; fn < 8; ++fn) {
            int bncol = bn0 + wn * 64 + fn * 8 + 2 * t;
            int b = bncol >> 12, n = bncol & 4095;
            #pragma unroll
            for (int rr = 0; rr < 2; ++rr) {
                int o = obase + rr * 8;
                float v0 = fmaxf(C[fm][fn][rr * 2 + 0] + (rr ? bias1 : bias0), 0.0f);
                float v1 = fmaxf(C[fm][fn][rr * 2 + 1] + (rr ? bias1 : bias0), 0.0f);
                if (o >= 64) {
                    *(uint32_t*)(g_Vb + ((size_t)b * CN + (o - 64)) * NN + n) = pack_bf2(v0, v1);
                } else {
                    #pragma unroll
                    for (int e = 0; e < 2; ++e) {
                        float v = e ? v1 : v0;
                        __nv_bfloat16 hi = __float2bfloat16(v);
                        __nv_bfloat16 lo = __float2bfloat16(v - __bfloat162float(hi));
                        size_t base = ((size_t)b * NN + n + e) * 128;
                        if (o < 32) {
                            g_Qb[base + o] = hi; g_Qb[base + 32 + o] = lo;
                            g_Qb[base + 64 + o] = hi; g_Qb[base + 96 + o] = zero;
                        } else {
                            int oc = o - 32;
                            g_Kb[base + oc] = hi; g_Kb[base + 32 + oc] = hi;
                            g_Kb[base + 64 + oc] = lo; g_Kb[base + 96 + oc] = zero;
                        }
                    }
                }
            }
        }
    }
}

// ---------------- flash attention: channel-major PV ----------------
// 8 warps: score role (mrow = wid&3 -> 16 q, khalf = wid>>2 -> 16 keys),
//          PV role (ch0 = wid*32 -> 32 channels, all 64 q).
// SMEM: Ks 2x[32][272B]@0, Vs 2x[256c][80B]@17408, Ps [64q][80B]@58368,
//       stM@63488, stL@64000, stF@64512, flags@64768, invl@64784.
#define KS_OFF 0
#define KS_BUF 8704
#define VS_OFF 17408
#define VS_BUF 20480
#define PS_OFF 58368
#define STM_OFF 63488
#define STL_OFF 64000
#define STF_OFF 64512
#define FLG_OFF 64768
#define INV_OFF 64784
#define SM_TOT 65280

__global__ void __launch_bounds__(256, 2)
flash_mma(const float* __restrict__ x, float* __restrict__ out) {
    extern __shared__ __align__(16) char smem[];
    uint32_t sb = smem_u32(smem);
    int tid = threadIdx.x;
    int lane = tid & 31, wid = tid >> 5;
    int g = lane >> 2, t = lane & 3;
    int mrow = wid & 3, khalf = wid >> 2;
    int q0 = mrow * 16;
    int ch0 = wid * 32;
    int b = blockIdx.y, m0 = blockIdx.x * 64;

    float* stM = (float*)(smem + STM_OFF);
    float* stL = (float*)(smem + STL_OFF);
    float* stF = (float*)(smem + STF_OFF);
    uint32_t* flg = (uint32_t*)(smem + FLG_OFF);
    float* inv = (float*)(smem + INV_OFF);

    uint32_t qa[6][4];
    {
        const __nv_bfloat16* qr0 = g_Qb + ((size_t)b * NN + m0 + q0 + g) * 128;
        const __nv_bfloat16* qr1 = qr0 + (size_t)8 * 128;
        #pragma unroll
        for (int ks = 0; ks < 6; ++ks) {
            int e = ks * 16 + 2 * t;
            qa[ks][0] = *(const uint32_t*)(qr0 + e);
            qa[ks][1] = *(const uint32_t*)(qr1 + e);
            qa[ks][2] = *(const uint32_t*)(qr0 + e + 8);
            qa[ks][3] = *(const uint32_t*)(qr1 + e + 8);
        }
    }

    const char* kgb = (const char*)(g_Kb + ((size_t)b * NN) * 128);
    const char* vgb = (const char*)(g_Vb + (size_t)b * CN * NN);

    {
        #pragma unroll
        for (int i = tid; i < 512; i += 256) {
            int row = i >> 4, col = i & 15;
            cp16(sb + KS_OFF + row * 272 + col * 16, kgb + (size_t)row * 256 + col * 16);
        }
        #pragma unroll
        for (int i = tid; i < 1024; i += 256) {
            int c = i >> 2, j = i & 3;
            cp16(sb + VS_OFF + c * 80 + j * 16, vgb + (size_t)c * (NN * 2) + j * 16);
        }
        CP_COMMIT();
    }

    float D[2][8][4];
    #pragma unroll
    for (int fm = 0; fm < 2; ++fm)
        #pragma unroll
        for (int fn = 0; fn < 8; ++fn) { D[fm][fn][0] = D[fm][fn][1] = D[fm][fn][2] = D[fm][fn][3] = 0.0f; }
    float m_run0 = -1e30f, m_run1 = -1e30f, l_run0 = 0.0f, l_run1 = 0.0f;

    for (int ch = 0; ch < 128; ++ch) {
        int buf = ch & 1;
        __syncthreads();   // B1: all consumers done with buf^1 + Ps/stF
        if (ch + 1 < 128) {
            int n1 = (ch + 1) * 32;
            uint32_t kd = sb + KS_OFF + (buf ^ 1) * KS_BUF;
            uint32_t vd = sb + VS_OFF + (buf ^ 1) * VS_BUF;
            #pragma unroll
            for (int i = tid; i < 512; i += 256) {
                int row = i >> 4, col = i & 15;
                cp16(kd + row * 272 + col * 16, kgb + (size_t)(n1 + row) * 256 + col * 16);
            }
            #pragma unroll
            for (int i = tid; i < 1024; i += 256) {
                int c = i >> 2, j = i & 3;
                cp16(vd + c * 80 + j * 16, vgb + (size_t)c * (NN * 2) + (size_t)n1 * 2 + j * 16);
            }
        }
        CP_COMMIT();
        CP_WAIT1();
        __syncthreads();   // B2: buf data visible

        // ---- score role: s[16q][16k] ----
        const char* ksm = smem + KS_OFF + buf * KS_BUF;
        float sc[2][4] = {};
        #pragma unroll
        for (int ks = 0; ks < 6; ++ks) {
            #pragma unroll
            for (int nt = 0; nt < 2; ++nt) {
                const char* kbase = ksm + (khalf * 16 + nt * 8 + g) * 272 + ks * 32 + t * 4;
                uint32_t b0 = *(const uint32_t*)(kbase);
                uint32_t b1 = *(const uint32_t*)(kbase + 16);
                mma_bf16_16816(sc[nt], qa[ks][0], qa[ks][1], qa[ks][2], qa[ks][3], b0, b1);
            }
        }
        float mp0 = fmaxf(fmaxf(sc[0][0], sc[0][1]), fmaxf(sc[1][0], sc[1][1]));
        float mp1 = fmaxf(fmaxf(sc[0][2], sc[0][3]), fmaxf(sc[1][2], sc[1][3]));
        mp0 = fmaxf(mp0, __shfl_xor_sync(0xffffffffu, mp0, 1));
        mp0 = fmaxf(mp0, __shfl_xor_sync(0xffffffffu, mp0, 2));
        mp1 = fmaxf(mp1, __shfl_xor_sync(0xffffffffu, mp1, 1));
        mp1 = fmaxf(mp1, __shfl_xor_sync(0xffffffffu, mp1, 2));
        if (t == 0) {
            stM[khalf * 64 + q0 + g] = mp0;
            stM[khalf * 64 + q0 + 8 + g] = mp1;
        }
        __syncthreads();   // B3: stM visible
        float mt0 = fmaxf(stM[q0 + g], stM[64 + q0 + g]);
        float mt1 = fmaxf(stM[q0 + 8 + g], stM[64 + q0 + 8 + g]);
        float mn0 = fmaxf(m_run0, mt0), mn1 = fmaxf(m_run1, mt1);
        float f0 = __expf(m_run0 - mn0), f1 = __expf(m_run1 - mn1);
        m_run0 = mn0; m_run1 = mn1;

        float e00 = __expf(sc[0][0] - mn0), e01 = __expf(sc[0][1] - mn0);
        float e02 = __expf(sc[0][2] - mn1), e03 = __expf(sc[0][3] - mn1);
        float e10 = __expf(sc[1][0] - mn0), e11 = __expf(sc[1][1] - mn0);
        float e12 = __expf(sc[1][2] - mn1), e13 = __expf(sc[1][3] - mn1);
        float ls0 = e00 + e01 + e10 + e11;
        float ls1 = e02 + e03 + e12 + e13;

        // publish P (own half), rescale factors, flag
        {
            char* pr0 = smem + PS_OFF + (q0 + g) * 80 + (khalf * 16 + 2 * t) * 2;
            char* pr1 = smem + PS_OFF + (q0 + 8 + g) * 80 + (khalf * 16 + 2 * t) * 2;
            *(uint32_t*)(pr0)      = pack_bf2(e00, e01);
            *(uint32_t*)(pr0 + 16) = pack_bf2(e10, e11);
            *(uint32_t*)(pr1)      = pack_bf2(e02, e03);
            *(uint32_t*)(pr1 + 16) = pack_bf2(e12, e13);
        }
        uint32_t nb = __ballot_sync(0xffffffffu, (f0 < 1.0f) || (f1 < 1.0f));
        if (khalf == 0 && t == 0) {
            stF[q0 + g] = f0;
            stF[q0 + 8 + g] = f1;
        }
        if (khalf == 0 && lane == 0) flg[mrow] = nb;
        ls0 += __shfl_xor_sync(0xffffffffu, ls0, 1);
        ls0 += __shfl_xor_sync(0xffffffffu, ls0, 2);
        ls1 += __shfl_xor_sync(0xffffffffu, ls1, 1);
        ls1 += __shfl_xor_sync(0xffffffffu, ls1, 2);
        if (t == 0) {
            stL[khalf * 64 + q0 + g] = ls0;
            stL[khalf * 64 + q0 + 8 + g] = ls1;
        }
        __syncthreads();   // B4: Ps both halves + stL + stF + flags visible
        l_run0 = l_run0 * f0 + stL[q0 + g] + stL[64 + q0 + g];
        l_run1 = l_run1 * f1 + stL[q0 + 8 + g] + stL[64 + q0 + 8 + g];

        // ---- PV role: D[32ch][64q] += V[32ch][32k] * P[32k][64q] ----
        if (flg[0] | flg[1] | flg[2] | flg[3]) {
            #pragma unroll
            for (int fn = 0; fn < 8; ++fn) {
                float2 ff = *(float2*)(stF + fn * 8 + 2 * t);
                #pragma unroll
                for (int fm = 0; fm < 2; ++fm) {
                    D[fm][fn][0] *= ff.x; D[fm][fn][1] *= ff.y;
                    D[fm][fn][2] *= ff.x; D[fm][fn][3] *= ff.y;
                }
            }
        }
        const char* vsm = smem + VS_OFF + buf * VS_BUF;
        uint32_t va[2][2][4];
        #pragma unroll
        for (int fm = 0; fm < 2; ++fm) {
            #pragma unroll
            for (int ks = 0; ks < 2; ++ks) {
                const char* vb = vsm + (ch0 + fm * 16 + g) * 80 + ks * 32 + t * 4;
                va[fm][ks][0] = *(const uint32_t*)(vb);
                va[fm][ks][1] = *(const uint32_t*)(vb + 8 * 80);
                va[fm][ks][2] = *(const uint32_t*)(vb + 16);
                va[fm][ks][3] = *(const uint32_t*)(vb + 8 * 80 + 16);
            }
        }
        #pragma unroll
        for (int fn = 0; fn < 8; ++fn) {
            const char* pb = smem + PS_OFF + (fn * 8 + g) * 80 + t * 4;
            #pragma unroll
            for (int ks = 0; ks < 2; ++ks) {
                uint32_t b0 = *(const uint32_t*)(pb + ks * 32);
                uint32_t b1 = *(const uint32_t*)(pb + ks * 32 + 16);
                mma_bf16_16816(D[0][fn], va[0][ks][0], va[0][ks][1], va[0][ks][2], va[0][ks][3], b0, b1);
                mma_bf16_16816(D[1][fn], va[1][ks][0], va[1][ks][1], va[1][ks][2], va[1][ks][3], b0, b1);
            }
        }
    }

    // publish final 1/l per query
    if (khalf == 0 && t == 0) {
        inv[q0 + g] = 1.0f / l_run0;
        inv[q0 + 8 + g] = 1.0f / l_run1;
    }
    __syncthreads();

    // ---- epilogue: out[ch][m0+q] = x + D * inv[q], direct coalesced ----
    const float* xb = x + (size_t)b * CN * NN + m0;
    float* ob = out + (size_t)b * CN * NN + m0;
    #pragma unroll
    for (int fn = 0; fn < 8; ++fn) {
        int q = fn * 8 + 2 * t;
        float2 iv = *(float2*)(inv + q);
        #pragma unroll
        for (int fm = 0; fm < 2; ++fm) {
            int chv = ch0 + fm * 16 + g;
            size_t o1 = (size_t)chv * NN + q;
            float2 x1 = *(const float2*)(xb + o1);
            float2 w1;
            w1.x = x1.x + D[fm][fn][0] * iv.x;
            w1.y = x1.y + D[fm][fn][1] * iv.y;
            *(float2*)(ob + o1) = w1;
            size_t o2 = (size_t)(chv + 8) * NN + q;
            float2 x2 = *(const float2*)(xb + o2);
            float2 w2;
            w2.x = x2.x + D[fm][fn][2] * iv.x;
            w2.y = x2.y + D[fm][fn][3] * iv.y;
            *(float2*)(ob + o2) = w2;
        }
    }
}

// ---------------- launcher ----------------
extern "C" void kernel_launch(void* const* d_in, const int* in_sizes, int n_in,
                              void* d_out, int out_size) {
    const float* x  = (const float*)d_in[0];
    const float* w1 = (const float*)d_in[1];
    const float* w2 = (const float*)d_in[2];
    const float* w3 = (const float*)d_in[3];
    const float* g1 = (const float*)d_in[4];
    const float* b1 = (const float*)d_in[5];
    const float* g2 = (const float*)d_in[6];
    const float* b2 = (const float*)d_in[7];
    const float* g3 = (const float*)d_in[8];
    const float* b3 = (const float*)d_in[9];
    float* out = (float*)d_out;

    cudaFuncSetAttribute(flash_mma, cudaFuncAttributeMaxDynamicSharedMemorySize, SM_TOT);
    cudaFuncSetAttribute(qkd_mma, cudaFuncAttributeMaxDynamicSharedMemorySize, QK_SM);

    zero_kernel<<<256, 256>>>();
    convx_kernel<<<dim3(64, 4, 4), 256>>>(x);
    gram_mma<<<dim3(4, 4, 16), 256>>>(0);
    fold_kernel<<<320, 256>>>(w1, w2, w3, g1, b1, g2, b2, g3, b3);
    qkd_mma<<<dim3(5, 64), 256, QK_SM>>>(0);
    flash_mma<<<dim3(64, 4), 256, SM_TOT>>>(x, out);
}

// round 10
// speedup vs baseline: 4.9564x; 1.1254x over previous
#include <cuda_runtime.h>
#include <cuda_bf16.h>
#include <cstdint>

#define BB 4
#define CN 256
#define NN 4096
#define OTOT 320
#define BN_TOT 16384.0f
#define KTOT 16384

// ---------------- device scratch ----------------
__device__ float g_mx[CN];                            // raw channel sums
__device__ float g_G[CN * CN];
__device__ float g_Bf[OTOT];
__device__ __nv_bfloat16 g_Wh[OTOT * CN];             // folded W hi, [o][c]
__device__ __nv_bfloat16 g_Wl[OTOT * CN];             // folded W lo, [o][c]
__device__ __nv_bfloat16 g_xh[(size_t)CN * KTOT];     // x hi, [c][b*n]
__device__ __nv_bfloat16 g_xl[(size_t)CN * KTOT];     // x lo, [c][b*n]
__device__ __nv_bfloat16 g_xTh[(size_t)KTOT * CN];    // x hi, [b*n][c]
__device__ __nv_bfloat16 g_xTl[(size_t)KTOT * CN];    // x lo, [b*n][c]
__device__ __nv_bfloat16 g_Qb[(size_t)BB * NN * 128]; // [b][n][qhi32|qlo32|qhi32|0]
__device__ __nv_bfloat16 g_Kb[(size_t)BB * NN * 128]; // [b][n][khi32|khi32|klo32|0]
__device__ __nv_bfloat16 g_Vb[(size_t)BB * CN * NN];  // bf16, [b][c][n]

// ---------------- mma.sync / async helpers ----------------
__device__ __forceinline__ void mma_bf16_16816(float* c, uint32_t a0, uint32_t a1,
                                               uint32_t a2, uint32_t a3,
                                               uint32_t b0, uint32_t b1) {
    asm volatile("mma.sync.aligned.m16n8k16.row.col.f32.bf16.bf16.f32 "
        "{%0,%1,%2,%3}, {%4,%5,%6,%7}, {%8,%9}, {%0,%1,%2,%3};"
        : "+f"(c[0]), "+f"(c[1]), "+f"(c[2]), "+f"(c[3])
        : "r"(a0), "r"(a1), "r"(a2), "r"(a3), "r"(b0), "r"(b1));
}
__device__ __forceinline__ void cp16(uint32_t dst, const void* src) {
    asm volatile("cp.async.cg.shared.global [%0], [%1], 16;" :: "r"(dst), "l"(src));
}
#define CP_COMMIT() asm volatile("cp.async.commit_group;" ::: "memory")
#define CP_WAIT0()  asm volatile("cp.async.wait_group 0;" ::: "memory")
#define CP_WAIT1()  asm volatile("cp.async.wait_group 1;" ::: "memory")
__device__ __forceinline__ uint32_t smem_u32(const void* p) {
    uint32_t a;
    asm("{ .reg .u64 t; cvta.to.shared.u64 t, %1; cvt.u32.u64 %0, t; }" : "=r"(a) : "l"(p));
    return a;
}
__device__ __forceinline__ uint32_t pack_bf2(float a, float b) {
    __nv_bfloat162 h = __floats2bfloat162_rn(a, b);
    return *(uint32_t*)&h;
}

// ---------------- prologue ----------------
__global__ void zero_kernel() {
    int i = blockIdx.x * blockDim.x + threadIdx.x;
    g_G[i] = 0.0f;
    if (i < CN) g_mx[i] = 0.0f;
}

// tiled transpose/convert: x -> bf16 hi/lo in [c][bn] AND [bn][c]; fused channel sums
__global__ void convx_kernel(const float* __restrict__ x) {
    __shared__ float tile[64][65];
    int n0 = blockIdx.x * 64, c0 = blockIdx.y * 64, b = blockIdx.z;
    int tid = threadIdx.x;
    int rr = tid >> 6, jj = tid & 63;
    const float* xb = x + ((size_t)b * CN + c0) * NN + n0;
    #pragma unroll
    for (int r = 0; r < 16; ++r) {
        int i = r * 4 + rr;
        tile[i][jj] = xb[(size_t)i * NN + jj];
    }
    __syncthreads();
    if (tid < 64) {
        float s = 0.0f;
        #pragma unroll
        for (int j = 0; j < 64; ++j) s += tile[tid][j];
        atomicAdd(&g_mx[c0 + tid], s);
    }
    size_t bn0 = (size_t)b * NN + n0;
    #pragma unroll
    for (int r = 0; r < 16; ++r) {
        int i = r * 4 + rr;
        float v = tile[i][jj];
        __nv_bfloat16 hi = __float2bfloat16(v);
        __nv_bfloat16 lo = __float2bfloat16(v - __bfloat162float(hi));
        size_t off = (size_t)(c0 + i) * KTOT + bn0 + jj;
        g_xh[off] = hi; g_xl[off] = lo;
    }
    #pragma unroll
    for (int r = 0; r < 16; ++r) {
        int i = r * 4 + rr;           // n index
        float v = tile[jj][i];        // [c=jj][n=i]
        __nv_bfloat16 hi = __float2bfloat16(v);
        __nv_bfloat16 lo = __float2bfloat16(v - __bfloat162float(hi));
        size_t off = (bn0 + i) * CN + c0 + jj;
        g_xTh[off] = hi; g_xTl[off] = lo;
    }
}

// ---------------- Gram via mma.sync (hi/lo bf16 compensation) ----------------
#define GR_STRIDE 144
#define GR_MAT (64 * GR_STRIDE)
__global__ void __launch_bounds__(256, 2)
gram_mma(int dummy) {
    __shared__ __align__(16) char smem[4 * GR_MAT];
    uint32_t sb = smem_u32(smem);
    int tid = threadIdx.x;
    int lane = tid & 31, wid = tid >> 5;
    int g = lane >> 2, t = lane & 3;
    int wm = wid >> 2, wn = wid & 3;
    int c0 = blockIdx.x * 64, c1 = blockIdx.y * 64;
    int kseg = blockIdx.z * 1024;

    float C[2][2][4] = {};

    for (int ch = 0; ch < 16; ++ch) {
        int k0 = kseg + ch * 64;
        __syncthreads();
        #pragma unroll
        for (int i = tid; i < 512; i += 256) {
            int row = i >> 3, col = i & 7;
            cp16(sb + 0 * GR_MAT + row * GR_STRIDE + col * 16,
                 g_xh + (size_t)(c0 + row) * KTOT + k0 + col * 8);
            cp16(sb + 1 * GR_MAT + row * GR_STRIDE + col * 16,
                 g_xl + (size_t)(c0 + row) * KTOT + k0 + col * 8);
            cp16(sb + 2 * GR_MAT + row * GR_STRIDE + col * 16,
                 g_xh + (size_t)(c1 + row) * KTOT + k0 + col * 8);
            cp16(sb + 3 * GR_MAT + row * GR_STRIDE + col * 16,
                 g_xl + (size_t)(c1 + row) * KTOT + k0 + col * 8);
        }
        CP_COMMIT();
        CP_WAIT0();
        __syncthreads();
        const char* Ah = smem;
        const char* Al = smem + GR_MAT;
        const char* Bh = smem + 2 * GR_MAT;
        const char* Bl = smem + 3 * GR_MAT;
        #pragma unroll
        for (int ks = 0; ks < 4; ++ks) {
            int koff = ks * 32 + t * 4;
            uint32_t ah[2][4], al[2][4];
            #pragma unroll
            for (int fm = 0; fm < 2; ++fm) {
                int r = wm * 32 + fm * 16 + g;
                ah[fm][0] = *(const uint32_t*)(Ah + r * GR_STRIDE + koff);
                ah[fm][1] = *(const uint32_t*)(Ah + (r + 8) * GR_STRIDE + koff);
                ah[fm][2] = *(const uint32_t*)(Ah + r * GR_STRIDE + koff + 16);
                ah[fm][3] = *(const uint32_t*)(Ah + (r + 8) * GR_STRIDE + koff + 16);
                al[fm][0] = *(const uint32_t*)(Al + r * GR_STRIDE + koff);
                al[fm][1] = *(const uint32_t*)(Al + (r + 8) * GR_STRIDE + koff);
                al[fm][2] = *(const uint32_t*)(Al + r * GR_STRIDE + koff + 16);
                al[fm][3] = *(const uint32_t*)(Al + (r + 8) * GR_STRIDE + koff + 16);
            }
            #pragma unroll
            for (int fn = 0; fn < 2; ++fn) {
                int r = wn * 16 + fn * 8 + g;
                uint32_t bh0 = *(const uint32_t*)(Bh + r * GR_STRIDE + koff);
                uint32_t bh1 = *(const uint32_t*)(Bh + r * GR_STRIDE + koff + 16);
                uint32_t bl0 = *(const uint32_t*)(Bl + r * GR_STRIDE + koff);
                uint32_t bl1 = *(const uint32_t*)(Bl + r * GR_STRIDE + koff + 16);
                #pragma unroll
                for (int fm = 0; fm < 2; ++fm) {
                    mma_bf16_16816(C[fm][fn], ah[fm][0], ah[fm][1], ah[fm][2], ah[fm][3], bh0, bh1);
                    mma_bf16_16816(C[fm][fn], ah[fm][0], ah[fm][1], ah[fm][2], ah[fm][3], bl0, bl1);
                    mma_bf16_16816(C[fm][fn], al[fm][0], al[fm][1], al[fm][2], al[fm][3], bh0, bh1);
                }
            }
        }
    }
    #pragma unroll
    for (int fm = 0; fm < 2; ++fm) {
        #pragma unroll
        for (int fn = 0; fn < 2; ++fn) {
            int r0 = c0 + wm * 32 + fm * 16 + g;
            int cc = c1 + wn * 16 + fn * 8 + 2 * t;
            atomicAdd(&g_G[r0 * CN + cc],           C[fm][fn][0]);
            atomicAdd(&g_G[r0 * CN + cc + 1],       C[fm][fn][1]);
            atomicAdd(&g_G[(r0 + 8) * CN + cc],     C[fm][fn][2]);
            atomicAdd(&g_G[(r0 + 8) * CN + cc + 1], C[fm][fn][3]);
        }
    }
}

// ---------------- fold BN, emit bf16 hi/lo weights ----------------
__global__ void fold_kernel(const float* __restrict__ w1, const float* __restrict__ w2,
                            const float* __restrict__ w3,
                            const float* __restrict__ g1, const float* __restrict__ b1,
                            const float* __restrict__ g2, const float* __restrict__ b2,
                            const float* __restrict__ g3, const float* __restrict__ b3) {
    int o = blockIdx.x, tid = threadIdx.x;
    const float* w; float gg, bb;
    if (o < 32)      { w = w1 + o * CN;        gg = g1[o];      bb = b1[o]; }
    else if (o < 64) { w = w2 + (o - 32) * CN; gg = g2[o - 32]; bb = b2[o - 32]; }
    else             { w = w3 + (o - 64) * CN; gg = g3[o - 64]; bb = b3[o - 64]; }
    __shared__ float ws[256], redE[256], redM[256], sc_sh;
    ws[tid] = w[tid]; __syncthreads();
    float a0 = 0.0f, a1 = 0.0f, a2 = 0.0f, a3 = 0.0f;
    #pragma unroll 8
    for (int c = 0; c < CN; c += 4) {
        a0 += g_G[(c + 0) * CN + tid] * ws[c + 0];
        a1 += g_G[(c + 1) * CN + tid] * ws[c + 1];
        a2 += g_G[(c + 2) * CN + tid] * ws[c + 2];
        a3 += g_G[(c + 3) * CN + tid] * ws[c + 3];
    }
    redE[tid] = (a0 + a1 + a2 + a3) * ws[tid];
    redM[tid] = ws[tid] * g_mx[tid] * (1.0f / BN_TOT);
    __syncthreads();
    for (int st = 128; st > 0; st >>= 1) {
        if (tid < st) { redE[tid] += redE[tid + st]; redM[tid] += redM[tid + st]; }
        __syncthreads();
    }
    if (tid == 0) {
        float m = redM[0], E = redE[0] * (1.0f / BN_TOT);
        float rs = rsqrtf(E - m * m + 1e-5f);
        float sc = gg * rs;
        sc_sh = sc;
        g_Bf[o] = bb - sc * m;
    }
    __syncthreads();
    float wf = sc_sh * ws[tid];
    __nv_bfloat16 hi = __float2bfloat16(wf);
    __nv_bfloat16 lo = __float2bfloat16(wf - __bfloat162float(hi));
    g_Wh[o * CN + tid] = hi;
    g_Wl[o * CN + tid] = lo;
}

// ---------------- qkd via mma.sync: Z[o][bn] = relu(W x + b) -> Qb/Kb/Vb ----------------
#define QK_SM 92160
__global__ void __launch_bounds__(256, 2)
qkd_mma(int dummy) {
    extern __shared__ __align__(16) char smem[];
    uint32_t sb = smem_u32(smem);
    int tid = threadIdx.x;
    int lane = tid & 31, wid = tid >> 5;
    int g = lane >> 2, t = lane & 3;
    int wm = wid >> 2, wn = wid & 3;
    int o0 = blockIdx.x * 64;
    int bn0 = blockIdx.y * 256;

    float C[2][8][4] = {};

    for (int kc = 0; kc < 4; ++kc) {
        int k0 = kc * 64;
        __syncthreads();
        #pragma unroll
        for (int i = tid; i < 512; i += 256) {
            int row = i >> 3, col = i & 7;
            cp16(sb + row * 144 + col * 16,        g_Wh + (size_t)(o0 + row) * CN + k0 + col * 8);
            cp16(sb + 9216 + row * 144 + col * 16, g_Wl + (size_t)(o0 + row) * CN + k0 + col * 8);
        }
        #pragma unroll
        for (int i = tid; i < 2048; i += 256) {
            int row = i >> 3, col = i & 7;
            cp16(sb + 18432 + row * 144 + col * 16, g_xTh + (bn0 + row) * (size_t)CN + k0 + col * 8);
            cp16(sb + 55296 + row * 144 + col * 16, g_xTl + (bn0 + row) * (size_t)CN + k0 + col * 8);
        }
        CP_COMMIT();
        CP_WAIT0();
        __syncthreads();
        const char* Wh = smem;
        const char* Wl = smem + 9216;
        const char* Xh = smem + 18432;
        const char* Xl = smem + 55296;
        #pragma unroll
        for (int ks = 0; ks < 4; ++ks) {
            int koff = ks * 32 + t * 4;
            uint32_t ah[2][4], al[2][4];
            #pragma unroll
            for (int fm = 0; fm < 2; ++fm) {
                int r = wm * 32 + fm * 16 + g;
                ah[fm][0] = *(const uint32_t*)(Wh + r * 144 + koff);
                ah[fm][1] = *(const uint32_t*)(Wh + (r + 8) * 144 + koff);
                ah[fm][2] = *(const uint32_t*)(Wh + r * 144 + koff + 16);
                ah[fm][3] = *(const uint32_t*)(Wh + (r + 8) * 144 + koff + 16);
                al[fm][0] = *(const uint32_t*)(Wl + r * 144 + koff);
                al[fm][1] = *(const uint32_t*)(Wl + (r + 8) * 144 + koff);
                al[fm][2] = *(const uint32_t*)(Wl + r * 144 + koff + 16);
                al[fm][3] = *(const uint32_t*)(Wl + (r + 8) * 144 + koff + 16);
            }
            #pragma unroll
            for (int fn = 0; fn < 8; ++fn) {
                int r = wn * 64 + fn * 8 + g;
                uint32_t bh0 = *(const uint32_t*)(Xh + r * 144 + koff);
                uint32_t bh1 = *(const uint32_t*)(Xh + r * 144 + koff + 16);
                uint32_t bl0 = *(const uint32_t*)(Xl + r * 144 + koff);
                uint32_t bl1 = *(const uint32_t*)(Xl + r * 144 + koff + 16);
                #pragma unroll
                for (int fm = 0; fm < 2; ++fm) {
                    mma_bf16_16816(C[fm][fn], ah[fm][0], ah[fm][1], ah[fm][2], ah[fm][3], bh0, bh1);
                    mma_bf16_16816(C[fm][fn], ah[fm][0], ah[fm][1], ah[fm][2], ah[fm][3], bl0, bl1);
                    mma_bf16_16816(C[fm][fn], al[fm][0], al[fm][1], al[fm][2], al[fm][3], bh0, bh1);
                }
            }
        }
    }

    __nv_bfloat16 zero = __float2bfloat16(0.0f);
    #pragma unroll
    for (int fm = 0; fm < 2; ++fm) {
        int obase = o0 + wm * 32 + fm * 16 + g;
        float bias0 = g_Bf[obase], bias1 = g_Bf[obase + 8];
        #pragma unroll
        for (int fn = 0; fn < 8; ++fn) {
            int bncol = bn0 + wn * 64 + fn * 8 + 2 * t;
            int b = bncol >> 12, n = bncol & 4095;
            #pragma unroll
            for (int rr = 0; rr < 2; ++rr) {
                int o = obase + rr * 8;
                float v0 = fmaxf(C[fm][fn][rr * 2 + 0] + (rr ? bias1 : bias0), 0.0f);
                float v1 = fmaxf(C[fm][fn][rr * 2 + 1] + (rr ? bias1 : bias0), 0.0f);
                if (o >= 64) {
                    *(uint32_t*)(g_Vb + ((size_t)b * CN + (o - 64)) * NN + n) = pack_bf2(v0, v1);
                } else {
                    #pragma unroll
                    for (int e = 0; e < 2; ++e) {
                        float v = e ? v1 : v0;
                        __nv_bfloat16 hi = __float2bfloat16(v);
                        __nv_bfloat16 lo = __float2bfloat16(v - __bfloat162float(hi));
                        size_t base = ((size_t)b * NN + n + e) * 128;
                        if (o < 32) {
                            g_Qb[base + o] = hi; g_Qb[base + 32 + o] = lo;
                            g_Qb[base + 64 + o] = hi; g_Qb[base + 96 + o] = zero;
                        } else {
                            int oc = o - 32;
                            g_Kb[base + oc] = hi; g_Kb[base + 32 + oc] = hi;
                            g_Kb[base + 64 + oc] = lo; g_Kb[base + 96 + oc] = zero;
                        }
                    }
                }
            }
        }
    }
}

// ---------------- flash attention: channel-major PV, NT=64 keys/chunk ----------------
// 8 warps: score role (mrow = wid&3 -> 16 q, khalf = wid>>2 -> 32 keys),
//          PV role (ch0 = wid*32 -> 32 channels, all 64 q, all 64 keys).
// SMEM: Ks 2x[64][208B]@0, Vs 2x[256c][144B]@26624, Ps [64q][144B]@100352,
//       stM@109568, stL@110080, stF@110592, flags@110848, invl@110864.
#define KS_OFF 0
#define KS_BUF 13312
#define VS_OFF 26624
#define VS_BUF 36864
#define PS_OFF 100352
#define STM_OFF 109568
#define STL_OFF 110080
#define STF_OFF 110592
#define FLG_OFF 110848
#define INV_OFF 110864
#define SM_TOT 111616

__global__ void __launch_bounds__(256, 2)
flash_mma(const float* __restrict__ x, float* __restrict__ out) {
    extern __shared__ __align__(16) char smem[];
    uint32_t sb = smem_u32(smem);
    int tid = threadIdx.x;
    int lane = tid & 31, wid = tid >> 5;
    int g = lane >> 2, t = lane & 3;
    int mrow = wid & 3, khalf = wid >> 2;
    int q0 = mrow * 16;
    int ch0 = wid * 32;
    int b = blockIdx.y, m0 = blockIdx.x * 64;

    float* stM = (float*)(smem + STM_OFF);
    float* stL = (float*)(smem + STL_OFF);
    float* stF = (float*)(smem + STF_OFF);
    uint32_t* flg = (uint32_t*)(smem + FLG_OFF);
    float* inv = (float*)(smem + INV_OFF);

    uint32_t qa[6][4];
    {
        const __nv_bfloat16* qr0 = g_Qb + ((size_t)b * NN + m0 + q0 + g) * 128;
        const __nv_bfloat16* qr1 = qr0 + (size_t)8 * 128;
        #pragma unroll
        for (int ks = 0; ks < 6; ++ks) {
            int e = ks * 16 + 2 * t;
            qa[ks][0] = *(const uint32_t*)(qr0 + e);
            qa[ks][1] = *(const uint32_t*)(qr1 + e);
            qa[ks][2] = *(const uint32_t*)(qr0 + e + 8);
            qa[ks][3] = *(const uint32_t*)(qr1 + e + 8);
        }
    }

    const char* kgb = (const char*)(g_Kb + ((size_t)b * NN) * 128);
    const char* vgb = (const char*)(g_Vb + (size_t)b * CN * NN);

    // prefetch chunk 0 into buf 0 (K: 64 rows x 12 cp16 = 192B data; V: 256 rows x 8 cp16)
    {
        #pragma unroll
        for (int i = tid; i < 768; i += 256) {
            int row = i / 12, col = i - row * 12;
            cp16(sb + KS_OFF + row * 208 + col * 16, kgb + (size_t)row * 256 + col * 16);
        }
        #pragma unroll
        for (int i = tid; i < 2048; i += 256) {
            int c = i >> 3, j = i & 7;
            cp16(sb + VS_OFF + c * 144 + j * 16, vgb + (size_t)c * (NN * 2) + j * 16);
        }
        CP_COMMIT();
    }

    float D[2][8][4];
    #pragma unroll
    for (int fm = 0; fm < 2; ++fm)
        #pragma unroll
        for (int fn = 0; fn < 8; ++fn) { D[fm][fn][0] = D[fm][fn][1] = D[fm][fn][2] = D[fm][fn][3] = 0.0f; }
    float m_run0 = -1e30f, m_run1 = -1e30f, l_run0 = 0.0f, l_run1 = 0.0f;

    for (int ch = 0; ch < 64; ++ch) {
        int buf = ch & 1;
        __syncthreads();   // B1: all consumers done with buf^1 + Ps/stF
        if (ch + 1 < 64) {
            int n1 = (ch + 1) * 64;
            uint32_t kd = sb + KS_OFF + (buf ^ 1) * KS_BUF;
            uint32_t vd = sb + VS_OFF + (buf ^ 1) * VS_BUF;
            #pragma unroll
            for (int i = tid; i < 768; i += 256) {
                int row = i / 12, col = i - row * 12;
                cp16(kd + row * 208 + col * 16, kgb + (size_t)(n1 + row) * 256 + col * 16);
            }
            #pragma unroll
            for (int i = tid; i < 2048; i += 256) {
                int c = i >> 3, j = i & 7;
                cp16(vd + c * 144 + j * 16, vgb + (size_t)c * (NN * 2) + (size_t)n1 * 2 + j * 16);
            }
        }
        CP_COMMIT();
        CP_WAIT1();
        __syncthreads();   // B2: buf data visible

        // ---- score role: s[16q][32k] (keys khalf*32..+32) ----
        const char* ksm = smem + KS_OFF + buf * KS_BUF;
        float sc[4][4] = {};
        #pragma unroll
        for (int ks = 0; ks < 6; ++ks) {
            #pragma unroll
            for (int nt = 0; nt < 4; ++nt) {
                const char* kbase = ksm + (khalf * 32 + nt * 8 + g) * 208 + ks * 32 + t * 4;
                uint32_t b0 = *(const uint32_t*)(kbase);
                uint32_t b1 = *(const uint32_t*)(kbase + 16);
                mma_bf16_16816(sc[nt], qa[ks][0], qa[ks][1], qa[ks][2], qa[ks][3], b0, b1);
            }
        }
        float mp0 = fmaxf(fmaxf(sc[0][0], sc[0][1]), fmaxf(sc[1][0], sc[1][1]));
        mp0 = fmaxf(mp0, fmaxf(fmaxf(sc[2][0], sc[2][1]), fmaxf(sc[3][0], sc[3][1])));
        float mp1 = fmaxf(fmaxf(sc[0][2], sc[0][3]), fmaxf(sc[1][2], sc[1][3]));
        mp1 = fmaxf(mp1, fmaxf(fmaxf(sc[2][2], sc[2][3]), fmaxf(sc[3][2], sc[3][3])));
        mp0 = fmaxf(mp0, __shfl_xor_sync(0xffffffffu, mp0, 1));
        mp0 = fmaxf(mp0, __shfl_xor_sync(0xffffffffu, mp0, 2));
        mp1 = fmaxf(mp1, __shfl_xor_sync(0xffffffffu, mp1, 1));
        mp1 = fmaxf(mp1, __shfl_xor_sync(0xffffffffu, mp1, 2));
        if (t == 0) {
            stM[khalf * 64 + q0 + g] = mp0;
            stM[khalf * 64 + q0 + 8 + g] = mp1;
        }
        __syncthreads();   // B3: stM visible
        float mt0 = fmaxf(stM[q0 + g], stM[64 + q0 + g]);
        float mt1 = fmaxf(stM[q0 + 8 + g], stM[64 + q0 + 8 + g]);
        float mn0 = fmaxf(m_run0, mt0), mn1 = fmaxf(m_run1, mt1);
        float f0 = __expf(m_run0 - mn0), f1 = __expf(m_run1 - mn1);
        m_run0 = mn0; m_run1 = mn1;

        float ls0 = 0.0f, ls1 = 0.0f;
        #pragma unroll
        for (int nt = 0; nt < 4; ++nt) {
            float e0 = __expf(sc[nt][0] - mn0);
            float e1 = __expf(sc[nt][1] - mn0);
            float e2 = __expf(sc[nt][2] - mn1);
            float e3 = __expf(sc[nt][3] - mn1);
            ls0 += e0 + e1; ls1 += e2 + e3;
            char* pr0 = smem + PS_OFF + (q0 + g) * 144 + khalf * 64 + nt * 16 + t * 4;
            char* pr1 = smem + PS_OFF + (q0 + 8 + g) * 144 + khalf * 64 + nt * 16 + t * 4;
            *(uint32_t*)(pr0) = pack_bf2(e0, e1);
            *(uint32_t*)(pr1) = pack_bf2(e2, e3);
        }
        uint32_t nb = __ballot_sync(0xffffffffu, (f0 < 1.0f) || (f1 < 1.0f));
        if (khalf == 0 && t == 0) {
            stF[q0 + g] = f0;
            stF[q0 + 8 + g] = f1;
        }
        if (khalf == 0 && lane == 0) flg[mrow] = nb;
        ls0 += __shfl_xor_sync(0xffffffffu, ls0, 1);
        ls0 += __shfl_xor_sync(0xffffffffu, ls0, 2);
        ls1 += __shfl_xor_sync(0xffffffffu, ls1, 1);
        ls1 += __shfl_xor_sync(0xffffffffu, ls1, 2);
        if (t == 0) {
            stL[khalf * 64 + q0 + g] = ls0;
            stL[khalf * 64 + q0 + 8 + g] = ls1;
        }
        __syncthreads();   // B4: Ps both halves + stL + stF + flags visible
        l_run0 = l_run0 * f0 + stL[q0 + g] + stL[64 + q0 + g];
        l_run1 = l_run1 * f1 + stL[q0 + 8 + g] + stL[64 + q0 + 8 + g];

        // ---- PV role: D[32ch][64q] += V[32ch][64k] * P[64k][64q] ----
        if (flg[0] | flg[1] | flg[2] | flg[3]) {
            #pragma unroll
            for (int fn = 0; fn < 8; ++fn) {
                float2 ff = *(float2*)(stF + fn * 8 + 2 * t);
                #pragma unroll
                for (int fm = 0; fm < 2; ++fm) {
                    D[fm][fn][0] *= ff.x; D[fm][fn][1] *= ff.y;
                    D[fm][fn][2] *= ff.x; D[fm][fn][3] *= ff.y;
                }
            }
        }
        const char* vsm = smem + VS_OFF + buf * VS_BUF;
        #pragma unroll
        for (int ks = 0; ks < 4; ++ks) {
            uint32_t va[2][4];
            #pragma unroll
            for (int fm = 0; fm < 2; ++fm) {
                const char* vb = vsm + (ch0 + fm * 16 + g) * 144 + ks * 32 + t * 4;
                va[fm][0] = *(const uint32_t*)(vb);
                va[fm][1] = *(const uint32_t*)(vb + 8 * 144);
                va[fm][2] = *(const uint32_t*)(vb + 16);
                va[fm][3] = *(const uint32_t*)(vb + 8 * 144 + 16);
            }
            #pragma unroll
            for (int fn = 0; fn < 8; ++fn) {
                const char* pb = smem + PS_OFF + (fn * 8 + g) * 144 + ks * 32 + t * 4;
                uint32_t b0 = *(const uint32_t*)(pb);
                uint32_t b1 = *(const uint32_t*)(pb + 16);
                mma_bf16_16816(D[0][fn], va[0][0], va[0][1], va[0][2], va[0][3], b0, b1);
                mma_bf16_16816(D[1][fn], va[1][0], va[1][1], va[1][2], va[1][3], b0, b1);
            }
        }
    }

    // publish final 1/l per query
    if (khalf == 0 && t == 0) {
        inv[q0 + g] = 1.0f / l_run0;
        inv[q0 + 8 + g] = 1.0f / l_run1;
    }
    __syncthreads();

    // ---- epilogue: out[ch][m0+q] = x + D * inv[q], direct coalesced ----
    const float* xb = x + (size_t)b * CN * NN + m0;
    float* ob = out + (size_t)b * CN * NN + m0;
    #pragma unroll
    for (int fn = 0; fn < 8; ++fn) {
        int q = fn * 8 + 2 * t;
        float2 iv = *(float2*)(inv + q);
        #pragma unroll
        for (int fm = 0; fm < 2; ++fm) {
            int chv = ch0 + fm * 16 + g;
            size_t o1 = (size_t)chv * NN + q;
            float2 x1 = *(const float2*)(xb + o1);
            float2 w1;
            w1.x = x1.x + D[fm][fn][0] * iv.x;
            w1.y = x1.y + D[fm][fn][1] * iv.y;
            *(float2*)(ob + o1) = w1;
            size_t o2 = (size_t)(chv + 8) * NN + q;
            float2 x2 = *(const float2*)(xb + o2);
            float2 w2;
            w2.x = x2.x + D[fm][fn][2] * iv.x;
            w2.y = x2.y + D[fm][fn][3] * iv.y;
            *(float2*)(ob + o2) = w2;
        }
    }
}

// ---------------- launcher ----------------
extern "C" void kernel_launch(void* const* d_in, const int* in_sizes, int n_in,
                              void* d_out, int out_size) {
    const float* x  = (const float*)d_in[0];
    const float* w1 = (const float*)d_in[1];
    const float* w2 = (const float*)d_in[2];
    const float* w3 = (const float*)d_in[3];
    const float* g1 = (const float*)d_in[4];
    const float* b1 = (const float*)d_in[5];
    const float* g2 = (const float*)d_in[6];
    const float* b2 = (const float*)d_in[7];
    const float* g3 = (const float*)d_in[8];
    const float* b3 = (const float*)d_in[9];
    float* out = (float*)d_out;

    cudaFuncSetAttribute(flash_mma, cudaFuncAttributeMaxDynamicSharedMemorySize, SM_TOT);
    cudaFuncSetAttribute(qkd_mma, cudaFuncAttributeMaxDynamicSharedMemorySize, QK_SM);

    zero_kernel<<<256, 256>>>();
    convx_kernel<<<dim3(64, 4, 4), 256>>>(x);
    gram_mma<<<dim3(4, 4, 16), 256>>>(0);
    fold_kernel<<<320, 256>>>(w1, w2, w3, g1, b1, g2, b2, g3, b3);
    qkd_mma<<<dim3(5, 64), 256, QK_SM>>>(0);
    flash_mma<<<dim3(64, 4), 256, SM_TOT>>>(x, out);
}